// round 1
// baseline (speedup 1.0000x reference)
#include <cuda_runtime.h>
#include <cuda_bf16.h>
#include <math.h>

// Problem constants
constexpr int Bv = 8;
constexpr int Tv = 2048;
constexpr int Cv = 1024;
constexpr int Hv = 64;
constexpr int Mtot = Bv * Tv;          // 16384 rows
constexpr float SCALE = 0.125f;        // 1/sqrt(64)

// Scratch for Q,K,V projections (4 MB each). __device__ globals per harness rules.
__device__ float g_Q[Mtot * Hv];
__device__ float g_K[Mtot * Hv];
__device__ float g_V[Mtot * Hv];

// ---------------------------------------------------------------------------
// Kernel 1: QKV projection GEMM. out[M,64] = x[M,1024] @ W[1024,64]
// BM=128, BN=64, BK=16; 256 threads as 16x16; each thread computes 8x4.
// blockIdx.y in {0,1,2} selects Wq/Wk/Wv -> g_Q/g_K/g_V.
// ---------------------------------------------------------------------------
__global__ __launch_bounds__(256) void proj_kernel(
    const float* __restrict__ x,
    const float* __restrict__ Wq,
    const float* __restrict__ Wk,
    const float* __restrict__ Wv)
{
    constexpr int BM = 128;
    constexpr int BK = 16;
    __shared__ float As[BK][BM];   // k-major
    __shared__ float Bs[BK][Hv];

    const int tx = threadIdx.x & 15;
    const int ty = threadIdx.x >> 4;
    const int m0 = blockIdx.x * BM;

    const float* W  = (blockIdx.y == 0) ? Wq : (blockIdx.y == 1) ? Wk : Wv;
    float*       out = (blockIdx.y == 0) ? g_Q : (blockIdx.y == 1) ? g_K : g_V;

    float acc[8][4];
#pragma unroll
    for (int i = 0; i < 8; i++)
#pragma unroll
        for (int j = 0; j < 4; j++) acc[i][j] = 0.f;

    for (int k0 = 0; k0 < Cv; k0 += BK) {
        __syncthreads();
        // Load A tile: rows m0..m0+127, cols k0..k0+15 (store k-major)
#pragma unroll
        for (int r = 0; r < 8; r++) {
            int row = r * 16 + ty;
            As[tx][row] = x[(size_t)(m0 + row) * Cv + k0 + tx];
        }
        // Load B tile: W[k0+kk][n]
#pragma unroll
        for (int r = 0; r < 4; r++) {
            Bs[ty][r * 16 + tx] = W[(size_t)(k0 + ty) * Hv + r * 16 + tx];
        }
        __syncthreads();

#pragma unroll
        for (int kk = 0; kk < BK; kk++) {
            float4 a0 = *(const float4*)&As[kk][ty * 8];
            float4 a1 = *(const float4*)&As[kk][ty * 8 + 4];
            float4 b4 = *(const float4*)&Bs[kk][tx * 4];
            float a[8] = {a0.x, a0.y, a0.z, a0.w, a1.x, a1.y, a1.z, a1.w};
            float bb[4] = {b4.x, b4.y, b4.z, b4.w};
#pragma unroll
            for (int i = 0; i < 8; i++)
#pragma unroll
                for (int j = 0; j < 4; j++)
                    acc[i][j] += a[i] * bb[j];
        }
    }

#pragma unroll
    for (int i = 0; i < 8; i++) {
        float4 o = make_float4(acc[i][0], acc[i][1], acc[i][2], acc[i][3]);
        *(float4*)&out[(size_t)(m0 + ty * 8 + i) * Hv + tx * 4] = o;
    }
}

// ---------------------------------------------------------------------------
// Kernel 2: causal flash attention (online softmax), fp32.
// Grid: (T/64, B). Block: 256 threads.
//   qi = tid & 63  : query within the 64-query tile
//   h  = tid >> 6  : 4-way key-tile split (thread h handles key tiles kt%4==h)
// Partials merged via shared memory at the end (tree merge: (0,1),(2,3),(0,2)).
// ---------------------------------------------------------------------------
__global__ __launch_bounds__(256) void attn_kernel(float* __restrict__ out)
{
    __shared__ float KVs[2 * 64 * 64];      // Ks = KVs[0..4095], Vs = KVs[4096..8191]; reused as merge buffer
    __shared__ float mred[4][64];
    __shared__ float lred[4][64];

    float* Ks = KVs;
    float* Vs = KVs + 4096;

    const int b     = blockIdx.y;
    const int qtile = blockIdx.x;
    const int tid   = threadIdx.x;
    const int qi    = tid & 63;
    const int h     = tid >> 6;
    const int q     = qtile * 64 + qi;

    // Load this thread's query row into registers
    float4 qv[16];
    const float4* qptr = (const float4*)(g_Q + (size_t)(b * Tv + q) * Hv);
#pragma unroll
    for (int i = 0; i < 16; i++) qv[i] = qptr[i];

    float4 av[16];
#pragma unroll
    for (int i = 0; i < 16; i++) av[i] = make_float4(0.f, 0.f, 0.f, 0.f);
    float m = -INFINITY, l = 0.f;

    const int ntiles = qtile + 1;
    for (int kt = 0; kt < ntiles; kt++) {
        __syncthreads();
        // Cooperative load of K and V tiles (64x64 floats each)
        const float4* Kg = (const float4*)(g_K + ((size_t)b * Tv + kt * 64) * Hv);
        const float4* Vg = (const float4*)(g_V + ((size_t)b * Tv + kt * 64) * Hv);
        float4* Ks4 = (float4*)Ks;
        float4* Vs4 = (float4*)Vs;
#pragma unroll
        for (int i = 0; i < 4; i++) {
            Ks4[tid + i * 256] = Kg[tid + i * 256];
            Vs4[tid + i * 256] = Vg[tid + i * 256];
        }
        __syncthreads();

        if ((kt & 3) == h) {
            const int jmax = min(63, q - kt * 64);   // kt*64 <= q guaranteed for assigned tiles
            for (int j = 0; j <= jmax; j++) {
                const float4* krow = (const float4*)&Ks[j * 64];
                float s0 = 0.f, s1 = 0.f, s2 = 0.f, s3 = 0.f;
#pragma unroll
                for (int d = 0; d < 16; d += 4) {
                    float4 k0 = krow[d], k1 = krow[d + 1], k2 = krow[d + 2], k3 = krow[d + 3];
                    s0 += qv[d].x     * k0.x + qv[d].y     * k0.y + qv[d].z     * k0.z + qv[d].w     * k0.w;
                    s1 += qv[d + 1].x * k1.x + qv[d + 1].y * k1.y + qv[d + 1].z * k1.z + qv[d + 1].w * k1.w;
                    s2 += qv[d + 2].x * k2.x + qv[d + 2].y * k2.y + qv[d + 2].z * k2.z + qv[d + 2].w * k2.w;
                    s3 += qv[d + 3].x * k3.x + qv[d + 3].y * k3.y + qv[d + 3].z * k3.z + qv[d + 3].w * k3.w;
                }
                float s = ((s0 + s1) + (s2 + s3)) * SCALE;

                float mnew = fmaxf(m, s);
                float corr = __expf(m - mnew);   // 0 when m == -inf
                float p    = __expf(s - mnew);
                l = l * corr + p;
                const float4* vrow = (const float4*)&Vs[j * 64];
#pragma unroll
                for (int d = 0; d < 16; d++) {
                    float4 vv = vrow[d];
                    av[d].x = av[d].x * corr + p * vv.x;
                    av[d].y = av[d].y * corr + p * vv.y;
                    av[d].z = av[d].z * corr + p * vv.z;
                    av[d].w = av[d].w * corr + p * vv.w;
                }
                m = mnew;
            }
        }
    }

    // ---- merge 4 partials per query: (0<-1), (2<-3), then (0<-2) ----
    __syncthreads();
    if (h == 1 || h == 3) {
        mred[h][qi] = m;
        lred[h][qi] = l;
        float4* dst = (float4*)(KVs + ((h >> 1) << 12) + qi * 64);
#pragma unroll
        for (int d = 0; d < 16; d++) dst[d] = av[d];
    }
    __syncthreads();
    if (h == 0 || h == 2) {
        float m2 = mred[h + 1][qi];
        float l2 = lred[h + 1][qi];
        const float4* src = (const float4*)(KVs + ((h >> 1) << 12) + qi * 64);
        float M = fmaxf(m, m2);
        if (M > -INFINITY) {
            float c1 = __expf(m - M);
            float c2 = __expf(m2 - M);
            l = l * c1 + l2 * c2;
#pragma unroll
            for (int d = 0; d < 16; d++) {
                float4 s4 = src[d];
                av[d].x = av[d].x * c1 + s4.x * c2;
                av[d].y = av[d].y * c1 + s4.y * c2;
                av[d].z = av[d].z * c1 + s4.z * c2;
                av[d].w = av[d].w * c1 + s4.w * c2;
            }
            m = M;
        }
    }
    __syncthreads();
    if (h == 2) {
        mred[2][qi] = m;
        lred[2][qi] = l;
        float4* dst = (float4*)(KVs + qi * 64);
#pragma unroll
        for (int d = 0; d < 16; d++) dst[d] = av[d];
    }
    __syncthreads();
    if (h == 0) {
        float m2 = mred[2][qi];
        float l2 = lred[2][qi];
        const float4* src = (const float4*)(KVs + qi * 64);
        float M  = fmaxf(m, m2);            // m is always finite for h==0
        float c1 = __expf(m - M);
        float c2 = __expf(m2 - M);          // 0 when m2 == -inf
        l = l * c1 + l2 * c2;
        float inv = 1.f / l;
        float4* op = (float4*)(out + (size_t)(b * Tv + q) * Hv);
#pragma unroll
        for (int d = 0; d < 16; d++) {
            float4 s4 = src[d];
            float4 o;
            o.x = (av[d].x * c1 + s4.x * c2) * inv;
            o.y = (av[d].y * c1 + s4.y * c2) * inv;
            o.z = (av[d].z * c1 + s4.z * c2) * inv;
            o.w = (av[d].w * c1 + s4.w * c2) * inv;
            op[d] = o;
        }
    }
}

// ---------------------------------------------------------------------------
extern "C" void kernel_launch(void* const* d_in, const int* in_sizes, int n_in,
                              void* d_out, int out_size)
{
    const float* x  = (const float*)d_in[0];
    const float* Wq = (const float*)d_in[1];
    const float* Wk = (const float*)d_in[2];
    const float* Wv = (const float*)d_in[3];
    float* out = (float*)d_out;

    dim3 g1(Mtot / 128, 3);
    proj_kernel<<<g1, 256>>>(x, Wq, Wk, Wv);

    dim3 g2(Tv / 64, Bv);
    attn_kernel<<<g2, 256>>>(out);
}

// round 3
// speedup vs baseline: 3.3642x; 3.3642x over previous
#include <cuda_runtime.h>
#include <math.h>

constexpr int Bv = 8, Tv = 2048, Cv = 1024, Hv = 64;
constexpr int Mtot = Bv * Tv;

__device__ float g_Q[Mtot * Hv];
__device__ float g_K[Mtot * Hv];
__device__ float g_V[Mtot * Hv];

__device__ __forceinline__ unsigned f2tf(float f) {
    unsigned u;
    asm("cvt.rna.tf32.f32 %0, %1;" : "=r"(u) : "f"(f));
    return u;
}

__device__ __forceinline__ void mma_tf32(float* c, const unsigned* a, const unsigned* b) {
    asm volatile(
        "mma.sync.aligned.m16n8k8.row.col.f32.tf32.tf32.f32 "
        "{%0,%1,%2,%3}, {%4,%5,%6,%7}, {%8,%9}, {%0,%1,%2,%3};"
        : "+f"(c[0]), "+f"(c[1]), "+f"(c[2]), "+f"(c[3])
        : "r"(a[0]), "r"(a[1]), "r"(a[2]), "r"(a[3]), "r"(b[0]), "r"(b[1]));
}

// ---------------------------------------------------------------------------
// Fused QKV projection: out[M,64] = x[M,1024] @ W[1024,64] for Wq,Wk,Wv.
// CTA: 128 threads (4 warps), BM=64 (warp m16), BK=64. tf32 mma, fp32 accum.
// ---------------------------------------------------------------------------
__global__ __launch_bounds__(128) void proj_kernel(
    const float* __restrict__ x,
    const float* __restrict__ Wq,
    const float* __restrict__ Wk,
    const float* __restrict__ Wv)
{
    extern __shared__ unsigned smem[];
    unsigned(*Xs)[65] = (unsigned(*)[65])smem;                       // 64*65
    unsigned(*Ws)[64][68] = (unsigned(*)[64][68])(smem + 64 * 65);   // 3*64*68

    const int t = threadIdx.x;
    const int lane = t & 31, w = t >> 5;
    const int g = lane >> 2, t4 = lane & 3;
    const int m0 = blockIdx.x * 64;
    const int xr = t & 63, xh = (t >> 6) * 32;   // X staging: row, col-half (32 wide)
    const int wk = t >> 1, wh = t & 1;           // W staging: row, col-half
    const float* Wp[3] = {Wq, Wk, Wv};

    float acc[3][8][4];
#pragma unroll
    for (int a = 0; a < 3; a++)
#pragma unroll
        for (int n = 0; n < 8; n++)
#pragma unroll
            for (int i = 0; i < 4; i++) acc[a][n][i] = 0.f;

    for (int k0 = 0; k0 < Cv; k0 += 64) {
        __syncthreads();
        // X tile -> Xs (tf32): each thread loads 32 floats (8 float4s)
        {
            const float4* xg = (const float4*)(x + (size_t)(m0 + xr) * Cv + k0 + xh);
#pragma unroll
            for (int i = 0; i < 8; i++) {
                float4 v = xg[i];
                Xs[xr][xh + 4 * i + 0] = f2tf(v.x);
                Xs[xr][xh + 4 * i + 1] = f2tf(v.y);
                Xs[xr][xh + 4 * i + 2] = f2tf(v.z);
                Xs[xr][xh + 4 * i + 3] = f2tf(v.w);
            }
        }
        // W tiles -> Ws: 128 threads * 32 = 4096 per matrix
#pragma unroll
        for (int w3 = 0; w3 < 3; w3++) {
            const float4* wg = (const float4*)(Wp[w3] + (size_t)(k0 + wk) * Hv + wh * 32);
#pragma unroll
            for (int i = 0; i < 8; i++) {
                float4 v = wg[i];
                Ws[w3][wk][wh * 32 + 4 * i + 0] = f2tf(v.x);
                Ws[w3][wk][wh * 32 + 4 * i + 1] = f2tf(v.y);
                Ws[w3][wk][wh * 32 + 4 * i + 2] = f2tf(v.z);
                Ws[w3][wk][wh * 32 + 4 * i + 3] = f2tf(v.w);
            }
        }
        __syncthreads();

#pragma unroll
        for (int ks = 0; ks < 8; ks++) {
            unsigned a[4];
            a[0] = Xs[w * 16 + g][ks * 8 + t4];
            a[1] = Xs[w * 16 + g + 8][ks * 8 + t4];
            a[2] = Xs[w * 16 + g][ks * 8 + t4 + 4];
            a[3] = Xs[w * 16 + g + 8][ks * 8 + t4 + 4];
#pragma unroll
            for (int w3 = 0; w3 < 3; w3++)
#pragma unroll
                for (int n = 0; n < 8; n++) {
                    unsigned bf[2] = {Ws[w3][ks * 8 + t4][n * 8 + g],
                                      Ws[w3][ks * 8 + t4 + 4][n * 8 + g]};
                    mma_tf32(acc[w3][n], a, bf);
                }
        }
    }

    float* outp[3] = {g_Q, g_K, g_V};
    const int r0 = m0 + w * 16 + g;
#pragma unroll
    for (int w3 = 0; w3 < 3; w3++)
#pragma unroll
        for (int n = 0; n < 8; n++) {
            *(float2*)&outp[w3][(size_t)r0 * Hv + n * 8 + 2 * t4] =
                make_float2(acc[w3][n][0], acc[w3][n][1]);
            *(float2*)&outp[w3][(size_t)(r0 + 8) * Hv + n * 8 + 2 * t4] =
                make_float2(acc[w3][n][2], acc[w3][n][3]);
        }
}

// ---------------------------------------------------------------------------
// Flash attention on tf32 mma. CTA: 128 threads (4 warps) = 64 queries;
// warp owns 16 query rows. Grid (32,8), heavy qtiles first.
// ---------------------------------------------------------------------------
__global__ __launch_bounds__(128) void attn_kernel(float* __restrict__ out)
{
    extern __shared__ unsigned smem[];
    unsigned(*Kt)[68] = (unsigned(*)[68])smem;               // [h][key]
    unsigned(*Vs)[68] = (unsigned(*)[68])(smem + 64 * 68);   // [key][h]
    unsigned* Pf = smem + 2 * 64 * 68;                       // [4][16][68] flat

    const int t = threadIdx.x, lane = t & 31, w = t >> 5;
    const int g = lane >> 2, t4 = lane & 3;
    const int b = blockIdx.y;
    const int qtile = 31 - blockIdx.x;     // heavy first
    const int q0 = qtile * 64;

    // ---- Q staging (scaled by 1/8, tf32) into Pf, then extract A-fragments ----
    {
        const int qr = t & 63, cb = (t >> 6) * 32;
        const float4* qg = (const float4*)(g_Q + (size_t)(b * Tv + q0 + qr) * Hv + cb);
#pragma unroll
        for (int i = 0; i < 8; i++) {
            float4 v = qg[i];
            Pf[qr * 68 + cb + 4 * i + 0] = f2tf(v.x * 0.125f);
            Pf[qr * 68 + cb + 4 * i + 1] = f2tf(v.y * 0.125f);
            Pf[qr * 68 + cb + 4 * i + 2] = f2tf(v.z * 0.125f);
            Pf[qr * 68 + cb + 4 * i + 3] = f2tf(v.w * 0.125f);
        }
    }
    __syncthreads();
    unsigned qa[8][4];
#pragma unroll
    for (int ks = 0; ks < 8; ks++) {
        qa[ks][0] = Pf[(w * 16 + g) * 68 + ks * 8 + t4];
        qa[ks][1] = Pf[(w * 16 + g + 8) * 68 + ks * 8 + t4];
        qa[ks][2] = Pf[(w * 16 + g) * 68 + ks * 8 + t4 + 4];
        qa[ks][3] = Pf[(w * 16 + g + 8) * 68 + ks * 8 + t4 + 4];
    }

    float o[8][4];
#pragma unroll
    for (int n = 0; n < 8; n++)
#pragma unroll
        for (int i = 0; i < 4; i++) o[n][i] = 0.f;
    float mrow0 = -INFINITY, mrow1 = -INFINITY, lrow0 = 0.f, lrow1 = 0.f;

    for (int kt = 0; kt <= qtile; kt++) {
        __syncthreads();   // prev compute done (covers Pf anti-dep too)
        // K tile, transposed store: Kt[h][key]; each thread: 32 cols of one key row
        {
            const int key = t & 63, cb = (t >> 6) * 32;
            const float4* kg = (const float4*)(g_K + (size_t)(b * Tv + kt * 64 + key) * Hv + cb);
#pragma unroll
            for (int i = 0; i < 8; i++) {
                float4 v = kg[i];
                Kt[cb + 4 * i + 0][key] = f2tf(v.x);
                Kt[cb + 4 * i + 1][key] = f2tf(v.y);
                Kt[cb + 4 * i + 2][key] = f2tf(v.z);
                Kt[cb + 4 * i + 3][key] = f2tf(v.w);
            }
        }
        // V tile, h-major loads, natural store: Vs[key][h]; 32 rows per thread
        {
            const int h = t & 63, kb = (t >> 6) * 32;
            const float* vg = g_V + (size_t)(b * Tv + kt * 64 + kb) * Hv + h;
#pragma unroll
            for (int i = 0; i < 32; i++)
                Vs[kb + i][h] = f2tf(vg[(size_t)i * Hv]);
        }
        __syncthreads();

        // ---- S = Q @ K^T ----
        float s[8][4];
#pragma unroll
        for (int n = 0; n < 8; n++)
#pragma unroll
            for (int i = 0; i < 4; i++) s[n][i] = 0.f;
#pragma unroll
        for (int ks = 0; ks < 8; ks++)
#pragma unroll
            for (int n = 0; n < 8; n++) {
                unsigned bf[2] = {Kt[ks * 8 + t4][n * 8 + g],
                                  Kt[ks * 8 + t4 + 4][n * 8 + g]};
                mma_tf32(s[n], qa[ks], bf);
            }

        // ---- causal mask on diagonal tile ----
        if (kt == qtile) {
            const int rl = w * 16 + g, rh = rl + 8;
#pragma unroll
            for (int n = 0; n < 8; n++) {
                const int c0 = n * 8 + 2 * t4;
                if (c0 > rl)     s[n][0] = -INFINITY;
                if (c0 + 1 > rl) s[n][1] = -INFINITY;
                if (c0 > rh)     s[n][2] = -INFINITY;
                if (c0 + 1 > rh) s[n][3] = -INFINITY;
            }
        }

        // ---- online softmax ----
        float mx0 = -INFINITY, mx1 = -INFINITY;
#pragma unroll
        for (int n = 0; n < 8; n++) {
            mx0 = fmaxf(mx0, fmaxf(s[n][0], s[n][1]));
            mx1 = fmaxf(mx1, fmaxf(s[n][2], s[n][3]));
        }
        mx0 = fmaxf(mx0, __shfl_xor_sync(0xffffffffu, mx0, 1));
        mx0 = fmaxf(mx0, __shfl_xor_sync(0xffffffffu, mx0, 2));
        mx1 = fmaxf(mx1, __shfl_xor_sync(0xffffffffu, mx1, 1));
        mx1 = fmaxf(mx1, __shfl_xor_sync(0xffffffffu, mx1, 2));

        const float mn0 = fmaxf(mrow0, mx0), mn1 = fmaxf(mrow1, mx1);
        const float c0f = __expf(mrow0 - mn0), c1f = __expf(mrow1 - mn1);
        float ls0 = 0.f, ls1 = 0.f;
#pragma unroll
        for (int n = 0; n < 8; n++) {
            s[n][0] = __expf(s[n][0] - mn0);
            s[n][1] = __expf(s[n][1] - mn0);
            s[n][2] = __expf(s[n][2] - mn1);
            s[n][3] = __expf(s[n][3] - mn1);
            ls0 += s[n][0] + s[n][1];
            ls1 += s[n][2] + s[n][3];
        }
        ls0 += __shfl_xor_sync(0xffffffffu, ls0, 1);
        ls0 += __shfl_xor_sync(0xffffffffu, ls0, 2);
        ls1 += __shfl_xor_sync(0xffffffffu, ls1, 1);
        ls1 += __shfl_xor_sync(0xffffffffu, ls1, 2);
        lrow0 = lrow0 * c0f + ls0;
        lrow1 = lrow1 * c1f + ls1;
        mrow0 = mn0;
        mrow1 = mn1;
#pragma unroll
        for (int n = 0; n < 8; n++) {
            o[n][0] *= c0f; o[n][1] *= c0f;
            o[n][2] *= c1f; o[n][3] *= c1f;
        }

        // ---- route P through warp-private smem (C-frag -> A-frag layout) ----
        unsigned* Pw = Pf + w * 16 * 68;
#pragma unroll
        for (int n = 0; n < 8; n++) {
            uint2 lo = make_uint2(f2tf(s[n][0]), f2tf(s[n][1]));
            uint2 hi = make_uint2(f2tf(s[n][2]), f2tf(s[n][3]));
            *(uint2*)&Pw[g * 68 + n * 8 + 2 * t4] = lo;
            *(uint2*)&Pw[(g + 8) * 68 + n * 8 + 2 * t4] = hi;
        }
        __syncwarp();

        // ---- O += P @ V ----
#pragma unroll
        for (int ks = 0; ks < 8; ks++) {
            unsigned pa[4];
            pa[0] = Pw[g * 68 + ks * 8 + t4];
            pa[1] = Pw[(g + 8) * 68 + ks * 8 + t4];
            pa[2] = Pw[g * 68 + ks * 8 + t4 + 4];
            pa[3] = Pw[(g + 8) * 68 + ks * 8 + t4 + 4];
#pragma unroll
            for (int n = 0; n < 8; n++) {
                unsigned bf[2] = {Vs[ks * 8 + t4][n * 8 + g],
                                  Vs[ks * 8 + t4 + 4][n * 8 + g]};
                mma_tf32(o[n], pa, bf);
            }
        }
    }

    // ---- epilogue: normalize and store ----
    const float inv0 = 1.f / lrow0, inv1 = 1.f / lrow1;
    const int r0 = b * Tv + q0 + w * 16 + g;
#pragma unroll
    for (int n = 0; n < 8; n++) {
        *(float2*)&out[(size_t)r0 * Hv + n * 8 + 2 * t4] =
            make_float2(o[n][0] * inv0, o[n][1] * inv0);
        *(float2*)&out[(size_t)(r0 + 8) * Hv + n * 8 + 2 * t4] =
            make_float2(o[n][2] * inv1, o[n][3] * inv1);
    }
}

// ---------------------------------------------------------------------------
extern "C" void kernel_launch(void* const* d_in, const int* in_sizes, int n_in,
                              void* d_out, int out_size)
{
    const float* x  = (const float*)d_in[0];
    const float* Wq = (const float*)d_in[1];
    const float* Wk = (const float*)d_in[2];
    const float* Wv = (const float*)d_in[3];
    float* out = (float*)d_out;

    const int proj_smem = (64 * 65 + 3 * 64 * 68) * 4;   // 68,864 B
    const int attn_smem = (3 * 64 * 68) * 4;             // 52,224 B
    cudaFuncSetAttribute(proj_kernel, cudaFuncAttributeMaxDynamicSharedMemorySize, proj_smem);
    cudaFuncSetAttribute(attn_kernel, cudaFuncAttributeMaxDynamicSharedMemorySize, attn_smem);

    proj_kernel<<<Mtot / 64, 128, proj_smem>>>(x, Wq, Wk, Wv);
    attn_kernel<<<dim3(32, Bv), 128, attn_smem>>>(out);
}

// round 4
// speedup vs baseline: 4.2602x; 1.2664x over previous
#include <cuda_runtime.h>
#include <math.h>

constexpr int Bv = 8, Tv = 2048, Cv = 1024, Hv = 64;
constexpr int Mtot = Bv * Tv;

__device__ float g_Q[Mtot * Hv];
__device__ float g_K[Mtot * Hv];
__device__ float g_V[Mtot * Hv];

__device__ __forceinline__ unsigned f2tf(float f) {
    unsigned u;
    asm("cvt.rna.tf32.f32 %0, %1;" : "=r"(u) : "f"(f));
    return u;
}

__device__ __forceinline__ void mma_tf32(float* c, const unsigned* a, const unsigned* b) {
    asm volatile(
        "mma.sync.aligned.m16n8k8.row.col.f32.tf32.tf32.f32 "
        "{%0,%1,%2,%3}, {%4,%5,%6,%7}, {%8,%9}, {%0,%1,%2,%3};"
        : "+f"(c[0]), "+f"(c[1]), "+f"(c[2]), "+f"(c[3])
        : "r"(a[0]), "r"(a[1]), "r"(a[2]), "r"(a[3]), "r"(b[0]), "r"(b[1]));
}

// XOR swizzle: tiles stored [row][col ^ ((row&3)<<3)], stride 64.
// B-frag reads (rows 8ks+t4, 8ks+t4+4 share row&3=t4) become conflict-free.

// ---------------------------------------------------------------------------
// Fused QKV projection. 256 thr / 8 warps. BM=64, BK=64.
// Warp w: m-tile (w&3), n-half (w>>2) [32 cols], all 3 matrices.
// ---------------------------------------------------------------------------
__global__ __launch_bounds__(256, 2) void proj_kernel(
    const float* __restrict__ x,
    const float* __restrict__ Wq,
    const float* __restrict__ Wk,
    const float* __restrict__ Wv)
{
    extern __shared__ unsigned smem[];
    unsigned* Xs = smem;                 // [64][65]
    unsigned* Wsb = smem + 64 * 65;      // [3][64][64] swizzled

    const int t = threadIdx.x, lane = t & 31, w = t >> 5;
    const int mt = w & 3, nh = w >> 2;
    const int g = lane >> 2, t4 = lane & 3;
    const int m0 = blockIdx.x * 64;
    const int sr = t & 63, sq = (t >> 6) * 16;   // staging row / col-quarter
    const float* Wp[3] = {Wq, Wk, Wv};

    float acc[3][4][4];
#pragma unroll
    for (int a = 0; a < 3; a++)
#pragma unroll
        for (int j = 0; j < 4; j++)
#pragma unroll
            for (int i = 0; i < 4; i++) acc[a][j][i] = 0.f;

    for (int k0 = 0; k0 < Cv; k0 += 64) {
        __syncthreads();
        // X tile -> Xs[64][65] (tf32), 16 elems/thread
        {
            const float4* xg = (const float4*)(x + (size_t)(m0 + sr) * Cv + k0 + sq);
#pragma unroll
            for (int i = 0; i < 4; i++) {
                float4 v = xg[i];
                Xs[sr * 65 + sq + 4 * i + 0] = f2tf(v.x);
                Xs[sr * 65 + sq + 4 * i + 1] = f2tf(v.y);
                Xs[sr * 65 + sq + 4 * i + 2] = f2tf(v.z);
                Xs[sr * 65 + sq + 4 * i + 3] = f2tf(v.w);
            }
        }
        // W tiles -> swizzled [64][64], 16 elems/thread per matrix
        const int sw = (sr & 3) << 3;
#pragma unroll
        for (int w3 = 0; w3 < 3; w3++) {
            const float4* wg = (const float4*)(Wp[w3] + (size_t)(k0 + sr) * Hv + sq);
            unsigned* Wm = Wsb + w3 * 4096 + sr * 64;
#pragma unroll
            for (int i = 0; i < 4; i++) {
                float4 v = wg[i];
                uint4 u = make_uint4(f2tf(v.x), f2tf(v.y), f2tf(v.z), f2tf(v.w));
                *(uint4*)&Wm[(sq + 4 * i) ^ sw] = u;
            }
        }
        __syncthreads();

#pragma unroll
        for (int ks = 0; ks < 8; ks++) {
            unsigned a[4];
            a[0] = Xs[(mt * 16 + g) * 65 + ks * 8 + t4];
            a[1] = Xs[(mt * 16 + g + 8) * 65 + ks * 8 + t4];
            a[2] = Xs[(mt * 16 + g) * 65 + ks * 8 + t4 + 4];
            a[3] = Xs[(mt * 16 + g + 8) * 65 + ks * 8 + t4 + 4];
            const int r0w = (ks * 8 + t4) * 64, r1w = (ks * 8 + t4 + 4) * 64;
#pragma unroll
            for (int w3 = 0; w3 < 3; w3++) {
                const unsigned* Wm = Wsb + w3 * 4096;
#pragma unroll
                for (int j = 0; j < 4; j++) {
                    const int n = nh * 4 + j;
                    const int cx = ((n ^ t4) << 3) + g;
                    unsigned bf[2] = {Wm[r0w + cx], Wm[r1w + cx]};
                    mma_tf32(acc[w3][j], a, bf);
                }
            }
        }
    }

    float* outp[3] = {g_Q, g_K, g_V};
    const int r0 = m0 + mt * 16 + g;
#pragma unroll
    for (int w3 = 0; w3 < 3; w3++)
#pragma unroll
        for (int j = 0; j < 4; j++) {
            const int n = nh * 4 + j;
            *(float2*)&outp[w3][(size_t)r0 * Hv + n * 8 + 2 * t4] =
                make_float2(acc[w3][j][0], acc[w3][j][1]);
            *(float2*)&outp[w3][(size_t)(r0 + 8) * Hv + n * 8 + 2 * t4] =
                make_float2(acc[w3][j][2], acc[w3][j][3]);
        }
}

// ---------------------------------------------------------------------------
// Flash attention. 256 thr / 8 warps = 2 groups of 4. Group p handles key
// tiles kt%2==p with private K/V buffers + named barrier; 2-way merge at end.
// ---------------------------------------------------------------------------
__global__ __launch_bounds__(256, 2) void attn_kernel(float* __restrict__ out)
{
    extern __shared__ unsigned smem[];
    // [0..16384): KV: grp0 {Kt,Vs}, grp1 {Kt,Vs}, each [64][64] swizzled
    // [16384..25088): Pf: per-warp [16][68] P-routing (also Q staging)
    unsigned* Pf = smem + 16384;

    const int t = threadIdx.x, lane = t & 31, w = t >> 5;
    const int wl = w & 3, grp = w >> 2;
    const int g = lane >> 2, t4 = lane & 3;
    const int gt = t & 127;

    // bid -> (batch, qtile): heavy singles on their own SM, pairs sum ~26
    const int bid = blockIdx.x;
    int qtile, b;
    if (bid < 108)      { qtile = bid % 27;      b = bid / 27; }
    else if (bid < 148) { int e = bid - 108; qtile = 27 + e % 5; b = e / 5; }
    else                { int v = 363 - bid; qtile = v % 27;     b = v / 27; }
    const int q0 = qtile * 64;

    unsigned* Kt = smem + grp * 8192;
    unsigned* Vs = Kt + 4096;
    unsigned* Pw = Pf + w * 16 * 68;

    // ---- Q staging (scaled, tf32) into Pf[64][68], then extract frags ----
    {
        const int qr = t & 63, cq = (t >> 6) * 16;
        const float4* qg = (const float4*)(g_Q + (size_t)(b * Tv + q0 + qr) * Hv + cq);
#pragma unroll
        for (int i = 0; i < 4; i++) {
            float4 v = qg[i];
            Pf[qr * 68 + cq + 4 * i + 0] = f2tf(v.x * 0.125f);
            Pf[qr * 68 + cq + 4 * i + 1] = f2tf(v.y * 0.125f);
            Pf[qr * 68 + cq + 4 * i + 2] = f2tf(v.z * 0.125f);
            Pf[qr * 68 + cq + 4 * i + 3] = f2tf(v.w * 0.125f);
        }
    }
    __syncthreads();
    unsigned qa[8][4];
#pragma unroll
    for (int ks = 0; ks < 8; ks++) {
        qa[ks][0] = Pf[(wl * 16 + g) * 68 + ks * 8 + t4];
        qa[ks][1] = Pf[(wl * 16 + g + 8) * 68 + ks * 8 + t4];
        qa[ks][2] = Pf[(wl * 16 + g) * 68 + ks * 8 + t4 + 4];
        qa[ks][3] = Pf[(wl * 16 + g + 8) * 68 + ks * 8 + t4 + 4];
    }
    __syncthreads();

    float o[8][4];
#pragma unroll
    for (int n = 0; n < 8; n++)
#pragma unroll
        for (int i = 0; i < 4; i++) o[n][i] = 0.f;
    float mrow0 = -INFINITY, mrow1 = -INFINITY, lrow0 = 0.f, lrow1 = 0.f;

    for (int kt = grp; kt <= qtile; kt += 2) {
        asm volatile("bar.sync %0, %1;" :: "r"(grp + 1), "r"(128) : "memory");
        // K tile -> Kt swizzled transposed: Kt[h][key^((h&3)<<3)]
        {
            const int key = gt & 63, cb = (gt >> 6) * 32;
            const float4* kg = (const float4*)(g_K + (size_t)(b * Tv + kt * 64 + key) * Hv + cb);
#pragma unroll
            for (int i = 0; i < 8; i++) {
                float4 v = kg[i];
                const int r = cb + 4 * i;
                Kt[(r + 0) * 64 + (key ^ 0)]  = f2tf(v.x);
                Kt[(r + 1) * 64 + (key ^ 8)]  = f2tf(v.y);
                Kt[(r + 2) * 64 + (key ^ 16)] = f2tf(v.z);
                Kt[(r + 3) * 64 + (key ^ 24)] = f2tf(v.w);
            }
        }
        // V tile -> Vs swizzled: Vs[key][h^((key&3)<<3)]
        {
            const int h = gt & 63, kb = (gt >> 6) * 32;
            const float* vg = g_V + (size_t)(b * Tv + kt * 64 + kb) * Hv + h;
#pragma unroll
            for (int i = 0; i < 32; i++) {
                const int r = kb + i;
                Vs[r * 64 + (h ^ ((r & 3) << 3))] = f2tf(vg[(size_t)i * Hv]);
            }
        }
        asm volatile("bar.sync %0, %1;" :: "r"(grp + 1), "r"(128) : "memory");

        // ---- S = Q @ K^T ----
        float s[8][4];
#pragma unroll
        for (int n = 0; n < 8; n++)
#pragma unroll
            for (int i = 0; i < 4; i++) s[n][i] = 0.f;
#pragma unroll
        for (int ks = 0; ks < 8; ks++) {
            const int r0w = (ks * 8 + t4) * 64, r1w = (ks * 8 + t4 + 4) * 64;
#pragma unroll
            for (int n = 0; n < 8; n++) {
                const int cx = ((n ^ t4) << 3) + g;
                unsigned bf[2] = {Kt[r0w + cx], Kt[r1w + cx]};
                mma_tf32(s[n], qa[ks], bf);
            }
        }

        // ---- causal mask on diagonal tile ----
        if (kt == qtile) {
            const int rl = wl * 16 + g, rh = rl + 8;
#pragma unroll
            for (int n = 0; n < 8; n++) {
                const int c0 = n * 8 + 2 * t4;
                if (c0 > rl)     s[n][0] = -INFINITY;
                if (c0 + 1 > rl) s[n][1] = -INFINITY;
                if (c0 > rh)     s[n][2] = -INFINITY;
                if (c0 + 1 > rh) s[n][3] = -INFINITY;
            }
        }

        // ---- online softmax ----
        float mx0 = -INFINITY, mx1 = -INFINITY;
#pragma unroll
        for (int n = 0; n < 8; n++) {
            mx0 = fmaxf(mx0, fmaxf(s[n][0], s[n][1]));
            mx1 = fmaxf(mx1, fmaxf(s[n][2], s[n][3]));
        }
        mx0 = fmaxf(mx0, __shfl_xor_sync(0xffffffffu, mx0, 1));
        mx0 = fmaxf(mx0, __shfl_xor_sync(0xffffffffu, mx0, 2));
        mx1 = fmaxf(mx1, __shfl_xor_sync(0xffffffffu, mx1, 1));
        mx1 = fmaxf(mx1, __shfl_xor_sync(0xffffffffu, mx1, 2));

        const float mn0 = fmaxf(mrow0, mx0), mn1 = fmaxf(mrow1, mx1);
        const float c0f = __expf(mrow0 - mn0), c1f = __expf(mrow1 - mn1);
        float ls0 = 0.f, ls1 = 0.f;
#pragma unroll
        for (int n = 0; n < 8; n++) {
            s[n][0] = __expf(s[n][0] - mn0);
            s[n][1] = __expf(s[n][1] - mn0);
            s[n][2] = __expf(s[n][2] - mn1);
            s[n][3] = __expf(s[n][3] - mn1);
            ls0 += s[n][0] + s[n][1];
            ls1 += s[n][2] + s[n][3];
        }
        ls0 += __shfl_xor_sync(0xffffffffu, ls0, 1);
        ls0 += __shfl_xor_sync(0xffffffffu, ls0, 2);
        ls1 += __shfl_xor_sync(0xffffffffu, ls1, 1);
        ls1 += __shfl_xor_sync(0xffffffffu, ls1, 2);
        lrow0 = lrow0 * c0f + ls0;
        lrow1 = lrow1 * c1f + ls1;
        mrow0 = mn0;
        mrow1 = mn1;
#pragma unroll
        for (int n = 0; n < 8; n++) {
            o[n][0] *= c0f; o[n][1] *= c0f;
            o[n][2] *= c1f; o[n][3] *= c1f;
        }

        // ---- route P through warp-private smem ----
#pragma unroll
        for (int n = 0; n < 8; n++) {
            *(uint2*)&Pw[g * 68 + n * 8 + 2 * t4] = make_uint2(f2tf(s[n][0]), f2tf(s[n][1]));
            *(uint2*)&Pw[(g + 8) * 68 + n * 8 + 2 * t4] = make_uint2(f2tf(s[n][2]), f2tf(s[n][3]));
        }
        __syncwarp();

        // ---- O += P @ V ----
#pragma unroll
        for (int ks = 0; ks < 8; ks++) {
            unsigned pa[4];
            pa[0] = Pw[g * 68 + ks * 8 + t4];
            pa[1] = Pw[(g + 8) * 68 + ks * 8 + t4];
            pa[2] = Pw[g * 68 + ks * 8 + t4 + 4];
            pa[3] = Pw[(g + 8) * 68 + ks * 8 + t4 + 4];
            const int r0w = (ks * 8 + t4) * 64, r1w = (ks * 8 + t4 + 4) * 64;
#pragma unroll
            for (int n = 0; n < 8; n++) {
                const int cx = ((n ^ t4) << 3) + g;
                unsigned bf[2] = {Vs[r0w + cx], Vs[r1w + cx]};
                mma_tf32(o[n], pa, bf);
            }
        }
    }

    // ---- 2-way merge (grp1 -> smem, grp0 combines + stores) ----
    __syncthreads();
    float* Ms = (float*)(smem + 8192);           // [64][66], in grp1's KV area
    float* Lm = (float*)(smem + 8192 + 64 * 66); // m[64], l[64]
    const int r0 = wl * 16 + g;
    if (grp == 1) {
        if (t4 == 0) {
            Lm[r0] = mrow0;       Lm[r0 + 8] = mrow1;
            Lm[64 + r0] = lrow0;  Lm[64 + r0 + 8] = lrow1;
        }
#pragma unroll
        for (int n = 0; n < 8; n++) {
            *(float2*)&Ms[r0 * 66 + n * 8 + 2 * t4] = make_float2(o[n][0], o[n][1]);
            *(float2*)&Ms[(r0 + 8) * 66 + n * 8 + 2 * t4] = make_float2(o[n][2], o[n][3]);
        }
    }
    __syncthreads();
    if (grp == 0) {
        const float m2a = Lm[r0], m2b = Lm[r0 + 8];
        const float l2a = Lm[64 + r0], l2b = Lm[64 + r0 + 8];
        const float M0 = fmaxf(mrow0, m2a), M1 = fmaxf(mrow1, m2b);
        const float c1a = __expf(mrow0 - M0), c2a = __expf(m2a - M0);
        const float c1b = __expf(mrow1 - M1), c2b = __expf(m2b - M1);
        const float inv0 = 1.f / (lrow0 * c1a + l2a * c2a);
        const float inv1 = 1.f / (lrow1 * c1b + l2b * c2b);
        const size_t ro = (size_t)(b * Tv + q0 + r0) * Hv;
#pragma unroll
        for (int n = 0; n < 8; n++) {
            float2 pa = *(float2*)&Ms[r0 * 66 + n * 8 + 2 * t4];
            float2 pb = *(float2*)&Ms[(r0 + 8) * 66 + n * 8 + 2 * t4];
            *(float2*)&out[ro + n * 8 + 2 * t4] =
                make_float2((o[n][0] * c1a + pa.x * c2a) * inv0,
                            (o[n][1] * c1a + pa.y * c2a) * inv0);
            *(float2*)&out[ro + 8 * Hv + n * 8 + 2 * t4] =
                make_float2((o[n][2] * c1b + pb.x * c2b) * inv1,
                            (o[n][3] * c1b + pb.y * c2b) * inv1);
        }
    }
}

// ---------------------------------------------------------------------------
extern "C" void kernel_launch(void* const* d_in, const int* in_sizes, int n_in,
                              void* d_out, int out_size)
{
    const float* x  = (const float*)d_in[0];
    const float* Wq = (const float*)d_in[1];
    const float* Wk = (const float*)d_in[2];
    const float* Wv = (const float*)d_in[3];
    float* out = (float*)d_out;

    const int proj_smem = (64 * 65 + 3 * 64 * 64) * 4;   // 65,792 B
    const int attn_smem = (4 * 64 * 64 + 8 * 16 * 68) * 4; // 100,352 B
    cudaFuncSetAttribute(proj_kernel, cudaFuncAttributeMaxDynamicSharedMemorySize, proj_smem);
    cudaFuncSetAttribute(attn_kernel, cudaFuncAttributeMaxDynamicSharedMemorySize, attn_smem);

    proj_kernel<<<Mtot / 64, 256, proj_smem>>>(x, Wq, Wk, Wv);
    attn_kernel<<<256, 256, attn_smem>>>(out);
}

// round 5
// speedup vs baseline: 4.9378x; 1.1590x over previous
#include <cuda_runtime.h>
#include <math.h>

constexpr int Bv = 8, Tv = 2048, Cv = 1024, Hv = 64;
constexpr int Mtot = Bv * Tv;

__device__ float g_Q[Mtot * Hv];
__device__ float g_K[Mtot * Hv];
__device__ float g_V[Mtot * Hv];

__device__ __forceinline__ unsigned f2tf(float f) {
    unsigned u;
    asm("cvt.rna.tf32.f32 %0, %1;" : "=r"(u) : "f"(f));
    return u;
}
__device__ __forceinline__ float ex2(float f) {
    float r;
    asm("ex2.approx.ftz.f32 %0, %1;" : "=f"(r) : "f"(f));
    return r;
}
__device__ __forceinline__ void mma_tf32(float* c, const unsigned* a, const unsigned* b) {
    asm volatile(
        "mma.sync.aligned.m16n8k8.row.col.f32.tf32.tf32.f32 "
        "{%0,%1,%2,%3}, {%4,%5,%6,%7}, {%8,%9}, {%0,%1,%2,%3};"
        : "+f"(c[0]), "+f"(c[1]), "+f"(c[2]), "+f"(c[3])
        : "r"(a[0]), "r"(a[1]), "r"(a[2]), "r"(a[3]), "r"(b[0]), "r"(b[1]));
}
#define BAR_SYNC(id)   asm volatile("bar.sync %0, %1;"   :: "r"(id), "r"(256) : "memory")
#define BAR_ARRIVE(id) asm volatile("bar.arrive %0, %1;" :: "r"(id), "r"(256) : "memory")
// full[p] = id 1+p, empty[p] = id 3+p

// ---------------------------------------------------------------------------
// Fused QKV projection, warp-specialized. 256 thr: warps 0-3 compute (m-tile
// each, all n, 3 mats), warps 4-7 produce X/W tiles, 2-stage, BK=32.
// ---------------------------------------------------------------------------
__global__ __launch_bounds__(256, 2) void proj_kernel(
    const float* __restrict__ x,
    const float* __restrict__ Wq,
    const float* __restrict__ Wk,
    const float* __restrict__ Wv)
{
    extern __shared__ unsigned smem[];
    // Xs: 2 stages of [64][33]; Ws: 2 stages of [3][32][64] swizzled
    unsigned* Xs0 = smem;                  // 2*2112
    unsigned* Ws0 = smem + 4224;           // 2*6144

    const int t = threadIdx.x, lane = t & 31, w = t >> 5;
    const int g = lane >> 2, t4 = lane & 3;
    const int m0 = blockIdx.x * 64;

    if (w < 4) {
        // ------------------ consumers ------------------
        const int mt = w;
        float acc[3][8][4];
#pragma unroll
        for (int a = 0; a < 3; a++)
#pragma unroll
            for (int n = 0; n < 8; n++)
#pragma unroll
                for (int i = 0; i < 4; i++) acc[a][n][i] = 0.f;

        for (int it = 0; it < 32; it++) {
            const int p = it & 1;
            const unsigned* Xp = Xs0 + p * 2112;
            const unsigned* Wp = Ws0 + p * 6144;
            BAR_SYNC(1 + p);
#pragma unroll
            for (int ks = 0; ks < 4; ks++) {
                unsigned a[4];
                a[0] = Xp[(mt * 16 + g) * 33 + ks * 8 + t4];
                a[1] = Xp[(mt * 16 + g + 8) * 33 + ks * 8 + t4];
                a[2] = Xp[(mt * 16 + g) * 33 + ks * 8 + t4 + 4];
                a[3] = Xp[(mt * 16 + g + 8) * 33 + ks * 8 + t4 + 4];
                const int r0w = (ks * 8 + t4) * 64, r1w = (ks * 8 + t4 + 4) * 64;
#pragma unroll
                for (int w3 = 0; w3 < 3; w3++) {
                    const unsigned* Wm = Wp + w3 * 2048;
#pragma unroll
                    for (int n = 0; n < 8; n++) {
                        const int cx = ((n ^ t4) << 3) + g;
                        unsigned bf[2] = {Wm[r0w + cx], Wm[r1w + cx]};
                        mma_tf32(acc[w3][n], a, bf);
                    }
                }
            }
            BAR_ARRIVE(3 + p);
        }

        float* outp[3] = {g_Q, g_K, g_V};
        const int r0 = m0 + mt * 16 + g;
#pragma unroll
        for (int w3 = 0; w3 < 3; w3++)
#pragma unroll
            for (int n = 0; n < 8; n++) {
                *(float2*)&outp[w3][(size_t)r0 * Hv + n * 8 + 2 * t4] =
                    make_float2(acc[w3][n][0], acc[w3][n][1]);
                *(float2*)&outp[w3][(size_t)(r0 + 8) * Hv + n * 8 + 2 * t4] =
                    make_float2(acc[w3][n][2], acc[w3][n][3]);
            }
    } else {
        // ------------------ producers ------------------
        const int gt = t - 128;
        const int xr = gt >> 1, xh = (gt & 1) * 16;   // X: row, col-half16
        const int wr = gt >> 2, wq = (gt & 3) * 16;   // W: row, col-quarter16
        const float* Wmat[3] = {Wq, Wk, Wv};
        for (int it = 0; it < 32; it++) {
            const int p = it & 1, k0 = it * 32;
            if (it >= 2) BAR_SYNC(3 + p);
            unsigned* Xp = Xs0 + p * 2112;
            unsigned* Wp = Ws0 + p * 6144;
            // X tile [64 rows][32 cols] -> Xs stride 33
            {
                const float4* xg = (const float4*)(x + (size_t)(m0 + xr) * Cv + k0 + xh);
#pragma unroll
                for (int i = 0; i < 4; i++) {
                    float4 v = xg[i];
                    unsigned* d = Xp + xr * 33 + xh + 4 * i;
                    d[0] = f2tf(v.x); d[1] = f2tf(v.y);
                    d[2] = f2tf(v.z); d[3] = f2tf(v.w);
                }
            }
            // W tiles [32 rows][64 cols] swizzled
            const int sw = (wr & 3) << 3;
#pragma unroll
            for (int w3 = 0; w3 < 3; w3++) {
                const float4* wg = (const float4*)(Wmat[w3] + (size_t)(k0 + wr) * Hv + wq);
                unsigned* Wm = Wp + w3 * 2048 + wr * 64;
#pragma unroll
                for (int i = 0; i < 4; i++) {
                    float4 v = wg[i];
                    *(uint4*)&Wm[(wq + 4 * i) ^ sw] =
                        make_uint4(f2tf(v.x), f2tf(v.y), f2tf(v.z), f2tf(v.w));
                }
            }
            BAR_ARRIVE(1 + p);
        }
    }
}

// ---------------------------------------------------------------------------
// Flash attention, warp-specialized. 256 thr: warps 0-3 compute (16 q-rows
// each), warps 4-7 produce K/V tiles (2-stage double buffer).
// ---------------------------------------------------------------------------
__global__ __launch_bounds__(256, 2) void attn_kernel(float* __restrict__ out)
{
    extern __shared__ unsigned smem[];
    // buf p at smem + p*8192: {Kt[64][64] swz, Vs[64][64] swz}
    unsigned* Pf = smem + 16384;           // [64][68]: Q staging, then per-warp P

    const int t = threadIdx.x, lane = t & 31, w = t >> 5;
    const int g = lane >> 2, t4 = lane & 3;

    // bid -> (batch, qtile): heavy singles own SM, pairs sum ~26
    const int bid = blockIdx.x;
    int qtile, b;
    if (bid < 108)      { qtile = bid % 27;      b = bid / 27; }
    else if (bid < 148) { int e = bid - 108; qtile = 27 + e % 5; b = e / 5; }
    else                { int v = 363 - bid; qtile = v % 27;     b = v / 27; }
    const int q0 = qtile * 64;

    // ---- Q staging by all threads (scaled by 0.125*log2(e), tf32) ----
    {
        const float qsc = 0.125f * 1.44269504f;
        const int qr = t & 63, cq = (t >> 6) * 16;
        const float4* qg = (const float4*)(g_Q + (size_t)(b * Tv + q0 + qr) * Hv + cq);
#pragma unroll
        for (int i = 0; i < 4; i++) {
            float4 v = qg[i];
            unsigned* d = Pf + qr * 68 + cq + 4 * i;
            d[0] = f2tf(v.x * qsc); d[1] = f2tf(v.y * qsc);
            d[2] = f2tf(v.z * qsc); d[3] = f2tf(v.w * qsc);
        }
    }
    __syncthreads();

    if (w < 4) {
        // ------------------ consumers ------------------
        unsigned* Pw = Pf + w * 16 * 68;
        unsigned qa[8][4];
#pragma unroll
        for (int ks = 0; ks < 8; ks++) {
            qa[ks][0] = Pf[(w * 16 + g) * 68 + ks * 8 + t4];
            qa[ks][1] = Pf[(w * 16 + g + 8) * 68 + ks * 8 + t4];
            qa[ks][2] = Pf[(w * 16 + g) * 68 + ks * 8 + t4 + 4];
            qa[ks][3] = Pf[(w * 16 + g + 8) * 68 + ks * 8 + t4 + 4];
        }

        float o[8][4];
#pragma unroll
        for (int n = 0; n < 8; n++)
#pragma unroll
            for (int i = 0; i < 4; i++) o[n][i] = 0.f;
        float mrow0 = -INFINITY, mrow1 = -INFINITY, lrow0 = 0.f, lrow1 = 0.f;

        for (int kt = 0; kt <= qtile; kt++) {
            const int p = kt & 1;
            const unsigned* Kt = smem + p * 8192;
            const unsigned* Vs = Kt + 4096;
            BAR_SYNC(1 + p);

            // S = Q @ K^T  (log2-domain scores)
            float s[8][4];
#pragma unroll
            for (int n = 0; n < 8; n++)
#pragma unroll
                for (int i = 0; i < 4; i++) s[n][i] = 0.f;
#pragma unroll
            for (int ks = 0; ks < 8; ks++) {
                const int r0w = (ks * 8 + t4) * 64, r1w = (ks * 8 + t4 + 4) * 64;
#pragma unroll
                for (int n = 0; n < 8; n++) {
                    const int cx = ((n ^ t4) << 3) + g;
                    unsigned bf[2] = {Kt[r0w + cx], Kt[r1w + cx]};
                    mma_tf32(s[n], qa[ks], bf);
                }
            }

            if (kt == qtile) {   // causal mask, diagonal tile
                const int rl = w * 16 + g, rh = rl + 8;
#pragma unroll
                for (int n = 0; n < 8; n++) {
                    const int c0 = n * 8 + 2 * t4;
                    if (c0 > rl)     s[n][0] = -INFINITY;
                    if (c0 + 1 > rl) s[n][1] = -INFINITY;
                    if (c0 > rh)     s[n][2] = -INFINITY;
                    if (c0 + 1 > rh) s[n][3] = -INFINITY;
                }
            }

            // online softmax (base 2)
            float mx0 = -INFINITY, mx1 = -INFINITY;
#pragma unroll
            for (int n = 0; n < 8; n++) {
                mx0 = fmaxf(mx0, fmaxf(s[n][0], s[n][1]));
                mx1 = fmaxf(mx1, fmaxf(s[n][2], s[n][3]));
            }
            mx0 = fmaxf(mx0, __shfl_xor_sync(0xffffffffu, mx0, 1));
            mx0 = fmaxf(mx0, __shfl_xor_sync(0xffffffffu, mx0, 2));
            mx1 = fmaxf(mx1, __shfl_xor_sync(0xffffffffu, mx1, 1));
            mx1 = fmaxf(mx1, __shfl_xor_sync(0xffffffffu, mx1, 2));

            const float mn0 = fmaxf(mrow0, mx0), mn1 = fmaxf(mrow1, mx1);
            const float c0f = ex2(mrow0 - mn0), c1f = ex2(mrow1 - mn1);
            float ls0 = 0.f, ls1 = 0.f;
#pragma unroll
            for (int n = 0; n < 8; n++) {
                s[n][0] = ex2(s[n][0] - mn0);
                s[n][1] = ex2(s[n][1] - mn0);
                s[n][2] = ex2(s[n][2] - mn1);
                s[n][3] = ex2(s[n][3] - mn1);
                ls0 += s[n][0] + s[n][1];
                ls1 += s[n][2] + s[n][3];
            }
            ls0 += __shfl_xor_sync(0xffffffffu, ls0, 1);
            ls0 += __shfl_xor_sync(0xffffffffu, ls0, 2);
            ls1 += __shfl_xor_sync(0xffffffffu, ls1, 1);
            ls1 += __shfl_xor_sync(0xffffffffu, ls1, 2);
            lrow0 = lrow0 * c0f + ls0;
            lrow1 = lrow1 * c1f + ls1;
            mrow0 = mn0;
            mrow1 = mn1;
#pragma unroll
            for (int n = 0; n < 8; n++) {
                o[n][0] *= c0f; o[n][1] *= c0f;
                o[n][2] *= c1f; o[n][3] *= c1f;
            }

            // route P through warp-private smem (C-frag -> A-frag)
#pragma unroll
            for (int n = 0; n < 8; n++) {
                *(uint2*)&Pw[g * 68 + n * 8 + 2 * t4] =
                    make_uint2(f2tf(s[n][0]), f2tf(s[n][1]));
                *(uint2*)&Pw[(g + 8) * 68 + n * 8 + 2 * t4] =
                    make_uint2(f2tf(s[n][2]), f2tf(s[n][3]));
            }
            __syncwarp();

            // O += P @ V
#pragma unroll
            for (int ks = 0; ks < 8; ks++) {
                unsigned pa[4];
                pa[0] = Pw[g * 68 + ks * 8 + t4];
                pa[1] = Pw[(g + 8) * 68 + ks * 8 + t4];
                pa[2] = Pw[g * 68 + ks * 8 + t4 + 4];
                pa[3] = Pw[(g + 8) * 68 + ks * 8 + t4 + 4];
                const int r0w = (ks * 8 + t4) * 64, r1w = (ks * 8 + t4 + 4) * 64;
#pragma unroll
                for (int n = 0; n < 8; n++) {
                    const int cx = ((n ^ t4) << 3) + g;
                    unsigned bf[2] = {Vs[r0w + cx], Vs[r1w + cx]};
                    mma_tf32(o[n], pa, bf);
                }
            }
            BAR_ARRIVE(3 + p);
        }

        // epilogue
        const float inv0 = 1.f / lrow0, inv1 = 1.f / lrow1;
        const size_t ro = (size_t)(b * Tv + q0 + w * 16 + g) * Hv;
#pragma unroll
        for (int n = 0; n < 8; n++) {
            *(float2*)&out[ro + n * 8 + 2 * t4] =
                make_float2(o[n][0] * inv0, o[n][1] * inv0);
            *(float2*)&out[ro + 8 * Hv + n * 8 + 2 * t4] =
                make_float2(o[n][2] * inv1, o[n][3] * inv1);
        }
    } else {
        // ------------------ producers ------------------
        const int gt = t - 128;
        for (int kt = 0; kt <= qtile; kt++) {
            const int p = kt & 1;
            if (kt >= 2) BAR_SYNC(3 + p);
            unsigned* Kt = smem + p * 8192;
            unsigned* Vs = Kt + 4096;
            // K tile -> transposed swizzled: Kt[h][key ^ ((h&3)<<3)]
            {
                const int key = gt & 63, cb = (gt >> 6) * 32;
                const float4* kg = (const float4*)(g_K + (size_t)(b * Tv + kt * 64 + key) * Hv + cb);
#pragma unroll
                for (int i = 0; i < 8; i++) {
                    float4 v = kg[i];
                    const int r = cb + 4 * i;
                    Kt[(r + 0) * 64 + (key ^ 0)]  = f2tf(v.x);
                    Kt[(r + 1) * 64 + (key ^ 8)]  = f2tf(v.y);
                    Kt[(r + 2) * 64 + (key ^ 16)] = f2tf(v.z);
                    Kt[(r + 3) * 64 + (key ^ 24)] = f2tf(v.w);
                }
            }
            // V tile -> Vs[key][h ^ ((key&3)<<3)]
            {
                const int h = gt & 63, kb = (gt >> 6) * 32;
                const float* vg = g_V + (size_t)(b * Tv + kt * 64 + kb) * Hv + h;
#pragma unroll
                for (int i = 0; i < 32; i++) {
                    const int r = kb + i;
                    Vs[r * 64 + (h ^ ((r & 3) << 3))] = f2tf(vg[(size_t)i * Hv]);
                }
            }
            BAR_ARRIVE(1 + p);
        }
    }
}

// ---------------------------------------------------------------------------
extern "C" void kernel_launch(void* const* d_in, const int* in_sizes, int n_in,
                              void* d_out, int out_size)
{
    const float* x  = (const float*)d_in[0];
    const float* Wq = (const float*)d_in[1];
    const float* Wk = (const float*)d_in[2];
    const float* Wv = (const float*)d_in[3];
    float* out = (float*)d_out;

    const int proj_smem = (2 * 64 * 33 + 2 * 3 * 32 * 64) * 4;   // 66,048 B
    const int attn_smem = (2 * 2 * 64 * 64 + 64 * 68) * 4;       // 82,944 B
    cudaFuncSetAttribute(proj_kernel, cudaFuncAttributeMaxDynamicSharedMemorySize, proj_smem);
    cudaFuncSetAttribute(attn_kernel, cudaFuncAttributeMaxDynamicSharedMemorySize, attn_smem);

    proj_kernel<<<Mtot / 64, 256, proj_smem>>>(x, Wq, Wk, Wv);
    attn_kernel<<<256, 256, attn_smem>>>(out);
}

// round 7
// speedup vs baseline: 6.3579x; 1.2876x over previous
#include <cuda_runtime.h>
#include <cstdint>
#include <math.h>

constexpr int Bv = 8, Tv = 2048, Cv = 1024, Hv = 64;
constexpr int Mtot = Bv * Tv;

__device__ float g_Q[Mtot * Hv];
__device__ float g_K[Mtot * Hv];
__device__ float g_V[Mtot * Hv];

__device__ __forceinline__ unsigned f2tf(float f) {
    unsigned u; asm("cvt.rna.tf32.f32 %0, %1;" : "=r"(u) : "f"(f)); return u;
}
__device__ __forceinline__ float ex2f(float f) {
    float r; asm("ex2.approx.ftz.f32 %0, %1;" : "=f"(r) : "f"(f)); return r;
}
__device__ __forceinline__ unsigned smem_u32(const void* p) {
    unsigned a; asm("{ .reg .u64 t; cvta.to.shared.u64 t, %1; cvt.u32.u64 %0, t; }" : "=r"(a) : "l"(p)); return a;
}
__device__ __forceinline__ void mma_tf32(float* c, const unsigned* a, const unsigned* b) {
    asm volatile(
        "mma.sync.aligned.m16n8k8.row.col.f32.tf32.tf32.f32 "
        "{%0,%1,%2,%3}, {%4,%5,%6,%7}, {%8,%9}, {%0,%1,%2,%3};"
        : "+f"(c[0]), "+f"(c[1]), "+f"(c[2]), "+f"(c[3])
        : "r"(a[0]), "r"(a[1]), "r"(a[2]), "r"(a[3]), "r"(b[0]), "r"(b[1]));
}
#define LDSM4(r0, r1, r2, r3, a) \
    asm volatile("ldmatrix.sync.aligned.m8n8.x4.shared.b16 {%0,%1,%2,%3}, [%4];" \
                 : "=r"(r0), "=r"(r1), "=r"(r2), "=r"(r3) : "r"(a))
#define BAR_SYNC(id)   asm volatile("bar.sync %0, %1;"   :: "r"(id), "r"(256) : "memory")
#define BAR_ARRIVE(id) asm volatile("bar.arrive %0, %1;" :: "r"(id), "r"(256) : "memory")

// ldmatrix.x4 lane-address constants:
//  B-frags (rows = n): matrices {rows 16jp..+7 klo, same khi, rows +8..15 klo, khi}
//  A-frags (rows = m): matrices {m-lo klo, m-hi klo, m-lo khi, m-hi khi}

// ---------------------------------------------------------------------------
// Fused QKV projection. 256 thr: warps 0-3 consume (m16 tile each, all n, all
// 3 matrices), warps 4-7 produce. 2-stage, BK=32. LDSM fragment loads.
// Xs: [64][36] rows=m (A-layout). Wt: [3][64][36] rows=n (B-layout, transposed).
// ---------------------------------------------------------------------------
__global__ __launch_bounds__(256, 2) void proj_kernel(
    const float* __restrict__ x,
    const float* __restrict__ Wq,
    const float* __restrict__ Wk,
    const float* __restrict__ Wv)
{
    extern __shared__ unsigned psmem[];
    const unsigned sb = smem_u32(psmem);
    const unsigned Xb = sb;              // 2 stages x 9216 B
    const unsigned Wb = sb + 18432;      // 2 stages x 27648 B

    const int t = threadIdx.x, lane = t & 31, w = t >> 5;
    const int g = lane >> 2, t4 = lane & 3;
    const int m0 = blockIdx.x * 64;

    if (w < 4) {
        // ------------------ consumers ------------------
        const int rbase  = ((lane >> 4) << 3) + (lane & 7);   // B rows
        const int coff   = ((lane >> 3) & 1) * 16;
        const int arbase = (((lane >> 3) & 1) << 3) + (lane & 7);  // A rows
        const int acoff  = (lane >> 4) * 16;
        const int mt = w;

        float acc[3][8][4];
#pragma unroll
        for (int a = 0; a < 3; a++)
#pragma unroll
            for (int n = 0; n < 8; n++)
#pragma unroll
                for (int i = 0; i < 4; i++) acc[a][n][i] = 0.f;

        for (int it = 0; it < 32; it++) {
            const int p = it & 1;
            BAR_SYNC(1 + p);
            const unsigned Xp = Xb + p * 9216;
            const unsigned Wp = Wb + p * 27648;
            const unsigned aaddr = Xp + (mt * 16 + arbase) * 144 + acoff;
            const unsigned baddr = Wp + rbase * 144 + coff;
#pragma unroll
            for (int ks = 0; ks < 4; ks++) {
                unsigned a[4];
                LDSM4(a[0], a[1], a[2], a[3], aaddr + ks * 32);
#pragma unroll
                for (int mat = 0; mat < 3; mat++) {
#pragma unroll
                    for (int jp = 0; jp < 4; jp++) {
                        unsigned b0, b1, b2, b3;
                        LDSM4(b0, b1, b2, b3, baddr + mat * 9216 + jp * 2304 + ks * 32);
                        unsigned blo[2] = {b0, b1}, bhi[2] = {b2, b3};
                        mma_tf32(acc[mat][2 * jp], a, blo);
                        mma_tf32(acc[mat][2 * jp + 1], a, bhi);
                    }
                }
            }
            BAR_ARRIVE(3 + p);
        }

        float* outp[3] = {g_Q, g_K, g_V};
        const int r0 = m0 + mt * 16 + g;
#pragma unroll
        for (int mat = 0; mat < 3; mat++)
#pragma unroll
            for (int n = 0; n < 8; n++) {
                *(float2*)&outp[mat][(size_t)r0 * Hv + n * 8 + 2 * t4] =
                    make_float2(acc[mat][n][0], acc[mat][n][1]);
                *(float2*)&outp[mat][(size_t)(r0 + 8) * Hv + n * 8 + 2 * t4] =
                    make_float2(acc[mat][n][2], acc[mat][n][3]);
            }
    } else {
        // ------------------ producers ------------------
        const int gt = t - 128;
        const int xr = gt >> 1, xs = gt & 1;        // X: row m, k-half16
        const int wn = gt & 63, wkh = (gt >> 6) * 16;  // W: col n, k-half16
        const float* Wmat[3] = {Wq, Wk, Wv};
        unsigned* Xw = psmem;                        // word view
        for (int it = 0; it < 32; it++) {
            const int p = it & 1, k0 = it * 32;
            if (it >= 2) BAR_SYNC(3 + p);
            unsigned* Xp = Xw + p * 2304;
            unsigned* Wp = Xw + 4608 + p * 6912;
            // X tile [64 m][32 k] -> rows stride 36, vectorized
            {
                const float4* xg = (const float4*)(x + (size_t)(m0 + xr) * Cv + k0 + 16 * xs);
#pragma unroll
                for (int c = 0; c < 4; c++) {
                    float4 v = xg[c];
                    *(uint4*)&Xp[xr * 36 + 16 * xs + 4 * c] =
                        make_uint4(f2tf(v.x), f2tf(v.y), f2tf(v.z), f2tf(v.w));
                }
            }
            // W tiles transposed: Wt[n][k], scalar scatter (coalesced LDG)
#pragma unroll
            for (int mat = 0; mat < 3; mat++) {
                const float* wg = Wmat[mat] + (size_t)(k0 + wkh) * Hv + wn;
                unsigned* Wd = Wp + mat * 2304 + wn * 36 + wkh;
#pragma unroll
                for (int j = 0; j < 16; j++)
                    Wd[j] = f2tf(wg[(size_t)j * Hv]);
            }
            BAR_ARRIVE(1 + p);
        }
    }
}

// ---------------------------------------------------------------------------
// Flash attention, warp-specialized + LDSM. 256 thr: warps 0-3 consume
// (16 q-rows each), warps 4-7 produce K/V (2-stage).
// Ks[key][h] rows stride 68 (B for S). Vt[h][key] stride 68 (B for PV).
// Qs[m][k] stride 68 (A for S). P per-warp [16][68] (A for PV).
// ---------------------------------------------------------------------------
__global__ __launch_bounds__(256, 2) void attn_kernel(float* __restrict__ out)
{
    extern __shared__ unsigned asmem[];
    const unsigned sb = smem_u32(asmem);
    const unsigned Kb0 = sb;             // 2 x 17408 B
    const unsigned Vb0 = sb + 34816;     // 2 x 17408 B
    const unsigned Qb  = sb + 69632;     // 17408 B
    const unsigned Pb  = sb + 87040;     // 4 x 4352 B

    const int t = threadIdx.x, lane = t & 31, w = t >> 5;
    const int g = lane >> 2, t4 = lane & 3;

    // bid -> (batch, qtile): heavy singles own SM, pairs sum ~26
    const int bid = blockIdx.x;
    int qtile, b;
    if (bid < 108)      { qtile = bid % 27;      b = bid / 27; }
    else if (bid < 148) { int e = bid - 108; qtile = 27 + e % 5; b = e / 5; }
    else                { int v = 363 - bid; qtile = v % 27;     b = v / 27; }
    const int q0 = qtile * 64;

    // ---- Q staging: [64][68], scale 0.125*log2(e) folded ----
    {
        const float qsc = 0.18033688f;
        const int qr = t >> 2, qs = t & 3;
        const float4* qg = (const float4*)(g_Q + (size_t)(b * Tv + q0 + qr) * Hv + 16 * qs);
        unsigned* qd = asmem + 17408 + qr * 68 + 16 * qs;   // Qb word offset 69632/4
#pragma unroll
        for (int c = 0; c < 4; c++) {
            float4 v = qg[c];
            *(uint4*)&qd[4 * c] = make_uint4(f2tf(v.x * qsc), f2tf(v.y * qsc),
                                             f2tf(v.z * qsc), f2tf(v.w * qsc));
        }
    }
    __syncthreads();

    if (w < 4) {
        // ------------------ consumers ------------------
        const int rbase  = ((lane >> 4) << 3) + (lane & 7);
        const int coff   = ((lane >> 3) & 1) * 16;
        const int arbase = (((lane >> 3) & 1) << 3) + (lane & 7);
        const int acoff  = (lane >> 4) * 16;
        const unsigned qaddr = Qb + (w * 16 + arbase) * 272 + acoff;
        const unsigned paddr = Pb + w * 4352 + arbase * 272 + acoff;
        unsigned* Pw = asmem + 21760 + w * 1088;   // word view of this warp's P

        float o[8][4];
#pragma unroll
        for (int n = 0; n < 8; n++)
#pragma unroll
            for (int i = 0; i < 4; i++) o[n][i] = 0.f;
        float mrow0 = -INFINITY, mrow1 = -INFINITY, lrow0 = 0.f, lrow1 = 0.f;

        for (int kt = 0; kt <= qtile; kt++) {
            const int p = kt & 1;
            BAR_SYNC(1 + p);
            const unsigned kaddr = Kb0 + p * 17408 + rbase * 272 + coff;
            const unsigned vaddr = Vb0 + p * 17408 + rbase * 272 + coff;

            // ---- S = Q @ K^T ----
            float s[8][4];
#pragma unroll
            for (int n = 0; n < 8; n++)
#pragma unroll
                for (int i = 0; i < 4; i++) s[n][i] = 0.f;
#pragma unroll
            for (int ks = 0; ks < 8; ks++) {
                unsigned qa[4];
                LDSM4(qa[0], qa[1], qa[2], qa[3], qaddr + ks * 32);
#pragma unroll
                for (int jp = 0; jp < 4; jp++) {
                    unsigned b0, b1, b2, b3;
                    LDSM4(b0, b1, b2, b3, kaddr + jp * 4352 + ks * 32);
                    unsigned blo[2] = {b0, b1}, bhi[2] = {b2, b3};
                    mma_tf32(s[2 * jp], qa, blo);
                    mma_tf32(s[2 * jp + 1], qa, bhi);
                }
            }

            if (kt == qtile) {   // causal mask, diagonal tile
                const int rl = w * 16 + g, rh = rl + 8;
#pragma unroll
                for (int n = 0; n < 8; n++) {
                    const int c0 = n * 8 + 2 * t4;
                    if (c0 > rl)     s[n][0] = -INFINITY;
                    if (c0 + 1 > rl) s[n][1] = -INFINITY;
                    if (c0 > rh)     s[n][2] = -INFINITY;
                    if (c0 + 1 > rh) s[n][3] = -INFINITY;
                }
            }

            // ---- online softmax (base 2) ----
            float mx0 = -INFINITY, mx1 = -INFINITY;
#pragma unroll
            for (int n = 0; n < 8; n++) {
                mx0 = fmaxf(mx0, fmaxf(s[n][0], s[n][1]));
                mx1 = fmaxf(mx1, fmaxf(s[n][2], s[n][3]));
            }
            mx0 = fmaxf(mx0, __shfl_xor_sync(0xffffffffu, mx0, 1));
            mx0 = fmaxf(mx0, __shfl_xor_sync(0xffffffffu, mx0, 2));
            mx1 = fmaxf(mx1, __shfl_xor_sync(0xffffffffu, mx1, 1));
            mx1 = fmaxf(mx1, __shfl_xor_sync(0xffffffffu, mx1, 2));

            const float mn0 = fmaxf(mrow0, mx0), mn1 = fmaxf(mrow1, mx1);
            const float c0f = ex2f(mrow0 - mn0), c1f = ex2f(mrow1 - mn1);
            float ls0 = 0.f, ls1 = 0.f;
#pragma unroll
            for (int n = 0; n < 8; n++) {
                s[n][0] = ex2f(s[n][0] - mn0);
                s[n][1] = ex2f(s[n][1] - mn0);
                s[n][2] = ex2f(s[n][2] - mn1);
                s[n][3] = ex2f(s[n][3] - mn1);
                ls0 += s[n][0] + s[n][1];
                ls1 += s[n][2] + s[n][3];
            }
            ls0 += __shfl_xor_sync(0xffffffffu, ls0, 1);
            ls0 += __shfl_xor_sync(0xffffffffu, ls0, 2);
            ls1 += __shfl_xor_sync(0xffffffffu, ls1, 1);
            ls1 += __shfl_xor_sync(0xffffffffu, ls1, 2);
            lrow0 = lrow0 * c0f + ls0;
            lrow1 = lrow1 * c1f + ls1;
            mrow0 = mn0;
            mrow1 = mn1;
#pragma unroll
            for (int n = 0; n < 8; n++) {
                o[n][0] *= c0f; o[n][1] *= c0f;
                o[n][2] *= c1f; o[n][3] *= c1f;
            }

            // ---- P -> warp-private smem [16][68] (A-layout: rows m, words k) ----
#pragma unroll
            for (int n = 0; n < 8; n++) {
                *(uint2*)&Pw[g * 68 + n * 8 + 2 * t4] =
                    make_uint2(f2tf(s[n][0]), f2tf(s[n][1]));
                *(uint2*)&Pw[(g + 8) * 68 + n * 8 + 2 * t4] =
                    make_uint2(f2tf(s[n][2]), f2tf(s[n][3]));
            }
            __syncwarp();

            // ---- O += P @ V ----
#pragma unroll
            for (int ks = 0; ks < 8; ks++) {
                unsigned pa[4];
                LDSM4(pa[0], pa[1], pa[2], pa[3], paddr + ks * 32);
#pragma unroll
                for (int jp = 0; jp < 4; jp++) {
                    unsigned b0, b1, b2, b3;
                    LDSM4(b0, b1, b2, b3, vaddr + jp * 4352 + ks * 32);
                    unsigned blo[2] = {b0, b1}, bhi[2] = {b2, b3};
                    mma_tf32(o[2 * jp], pa, blo);
                    mma_tf32(o[2 * jp + 1], pa, bhi);
                }
            }
            BAR_ARRIVE(3 + p);
        }

        // ---- epilogue ----
        const float inv0 = 1.f / lrow0, inv1 = 1.f / lrow1;
        const size_t ro = (size_t)(b * Tv + q0 + w * 16 + g) * Hv;
#pragma unroll
        for (int n = 0; n < 8; n++) {
            *(float2*)&out[ro + n * 8 + 2 * t4] =
                make_float2(o[n][0] * inv0, o[n][1] * inv0);
            *(float2*)&out[ro + 8 * Hv + n * 8 + 2 * t4] =
                make_float2(o[n][2] * inv1, o[n][3] * inv1);
        }
    } else {
        // ------------------ producers ------------------
        const int pt = t - 128;
        for (int kt = 0; kt <= qtile; kt++) {
            const int p = kt & 1;
            if (kt >= 2) BAR_SYNC(3 + p);
            unsigned* Kp = asmem + p * 4352;
            unsigned* Vp = asmem + 8704 + p * 4352;
            // K tile natural: Ks[key][h], rows stride 68, vectorized
            {
                const int key = pt >> 1, s = pt & 1;
                const float4* kg = (const float4*)(g_K + (size_t)(b * Tv + kt * 64 + key) * Hv + 32 * s);
#pragma unroll
                for (int c = 0; c < 8; c++) {
                    float4 v = kg[c];
                    *(uint4*)&Kp[key * 68 + 32 * s + 4 * c] =
                        make_uint4(f2tf(v.x), f2tf(v.y), f2tf(v.z), f2tf(v.w));
                }
            }
            // V tile transposed: Vt[h][key], scalar scatter (coalesced LDG)
            {
                const int h = pt & 63, s = pt >> 6;
                const float* vg = g_V + (size_t)(b * Tv + kt * 64 + 32 * s) * Hv + h;
                unsigned* Vd = Vp + h * 68 + 32 * s;
#pragma unroll
                for (int j = 0; j < 32; j++)
                    Vd[j] = f2tf(vg[(size_t)j * Hv]);
            }
            BAR_ARRIVE(1 + p);
        }
    }
}

// ---------------------------------------------------------------------------
extern "C" void kernel_launch(void* const* d_in, const int* in_sizes, int n_in,
                              void* d_out, int out_size)
{
    const float* x  = (const float*)d_in[0];
    const float* Wq = (const float*)d_in[1];
    const float* Wk = (const float*)d_in[2];
    const float* Wv = (const float*)d_in[3];
    float* out = (float*)d_out;

    const int proj_smem = 18432 + 55296;          // 73,728 B
    const int attn_smem = 34816 * 2 + 17408 * 2;  // 104,448 B
    cudaFuncSetAttribute(proj_kernel, cudaFuncAttributeMaxDynamicSharedMemorySize, proj_smem);
    cudaFuncSetAttribute(attn_kernel, cudaFuncAttributeMaxDynamicSharedMemorySize, attn_smem);

    proj_kernel<<<Mtot / 64, 256, proj_smem>>>(x, Wq, Wk, Wv);
    attn_kernel<<<256, 256, attn_smem>>>(out);
}

// round 8
// speedup vs baseline: 6.5258x; 1.0264x over previous
#include <cuda_runtime.h>
#include <cstdint>
#include <math.h>

constexpr int Bv = 8, Tv = 2048, Cv = 1024, Hv = 64;
constexpr int Mtot = Bv * Tv;

__device__ float g_Q[Mtot * Hv];    // tf32 bits, pre-scaled by 0.125*log2(e)
__device__ float g_K[Mtot * Hv];    // tf32 bits
__device__ float g_V[Mtot * Hv];    // fp32 (from proj)
__device__ float g_Vt[Bv * Hv * Tv];// tf32 bits, transposed [b*64+h][token]

__device__ __forceinline__ unsigned f2tf(float f) {
    unsigned u; asm("cvt.rna.tf32.f32 %0, %1;" : "=r"(u) : "f"(f)); return u;
}
__device__ __forceinline__ float ex2f(float f) {
    float r; asm("ex2.approx.ftz.f32 %0, %1;" : "=f"(r) : "f"(f)); return r;
}
__device__ __forceinline__ unsigned smem_u32(const void* p) {
    unsigned a; asm("{ .reg .u64 t; cvta.to.shared.u64 t, %1; cvt.u32.u64 %0, t; }" : "=r"(a) : "l"(p)); return a;
}
__device__ __forceinline__ void mma_tf32(float* c, const unsigned* a, const unsigned* b) {
    asm volatile(
        "mma.sync.aligned.m16n8k8.row.col.f32.tf32.tf32.f32 "
        "{%0,%1,%2,%3}, {%4,%5,%6,%7}, {%8,%9}, {%0,%1,%2,%3};"
        : "+f"(c[0]), "+f"(c[1]), "+f"(c[2]), "+f"(c[3])
        : "r"(a[0]), "r"(a[1]), "r"(a[2]), "r"(a[3]), "r"(b[0]), "r"(b[1]));
}
#define LDSM4(r0, r1, r2, r3, a) \
    asm volatile("ldmatrix.sync.aligned.m8n8.x4.shared.b16 {%0,%1,%2,%3}, [%4];" \
                 : "=r"(r0), "=r"(r1), "=r"(r2), "=r"(r3) : "r"(a))
#define BAR_SYNC(id)   asm volatile("bar.sync %0, %1;"   :: "r"(id), "r"(256) : "memory")
#define BAR_ARRIVE(id) asm volatile("bar.arrive %0, %1;" :: "r"(id), "r"(256) : "memory")
#define CP_ASYNC16(s, g) asm volatile("cp.async.cg.shared.global [%0], [%1], 16;" :: "r"(s), "l"(g))
#define CP_COMMIT()      asm volatile("cp.async.commit_group;" ::: "memory")
#define CP_WAIT1()       asm volatile("cp.async.wait_group 1;" ::: "memory")

constexpr float QSC = 0.18033688f;   // 0.125 * log2(e)
constexpr float NEG = -1e30f;

// ---------------------------------------------------------------------------
// Fused QKV projection (R7 structure; epilogue now emits tf32 for Q,K and
// pre-scales Q by 0.125*log2e).
// ---------------------------------------------------------------------------
__global__ __launch_bounds__(256, 2) void proj_kernel(
    const float* __restrict__ x,
    const float* __restrict__ Wq,
    const float* __restrict__ Wk,
    const float* __restrict__ Wv)
{
    extern __shared__ unsigned psmem[];
    const unsigned sb = smem_u32(psmem);
    const unsigned Xb = sb;              // 2 stages x 9216 B
    const unsigned Wb = sb + 18432;      // 2 stages x 27648 B

    const int t = threadIdx.x, lane = t & 31, w = t >> 5;
    const int g = lane >> 2, t4 = lane & 3;
    const int m0 = blockIdx.x * 64;

    if (w < 4) {
        const int rbase  = ((lane >> 4) << 3) + (lane & 7);
        const int coff   = ((lane >> 3) & 1) * 16;
        const int arbase = (((lane >> 3) & 1) << 3) + (lane & 7);
        const int acoff  = (lane >> 4) * 16;
        const int mt = w;

        float acc[3][8][4];
#pragma unroll
        for (int a = 0; a < 3; a++)
#pragma unroll
            for (int n = 0; n < 8; n++)
#pragma unroll
                for (int i = 0; i < 4; i++) acc[a][n][i] = 0.f;

        for (int it = 0; it < 32; it++) {
            const int p = it & 1;
            BAR_SYNC(1 + p);
            const unsigned Xp = Xb + p * 9216;
            const unsigned Wp = Wb + p * 27648;
            const unsigned aaddr = Xp + (mt * 16 + arbase) * 144 + acoff;
            const unsigned baddr = Wp + rbase * 144 + coff;
#pragma unroll
            for (int ks = 0; ks < 4; ks++) {
                unsigned a[4];
                LDSM4(a[0], a[1], a[2], a[3], aaddr + ks * 32);
#pragma unroll
                for (int mat = 0; mat < 3; mat++) {
#pragma unroll
                    for (int jp = 0; jp < 4; jp++) {
                        unsigned b0, b1, b2, b3;
                        LDSM4(b0, b1, b2, b3, baddr + mat * 9216 + jp * 2304 + ks * 32);
                        unsigned blo[2] = {b0, b1}, bhi[2] = {b2, b3};
                        mma_tf32(acc[mat][2 * jp], a, blo);
                        mma_tf32(acc[mat][2 * jp + 1], a, bhi);
                    }
                }
            }
            BAR_ARRIVE(3 + p);
        }

        const int r0 = m0 + mt * 16 + g;
        // Q: tf32(acc * QSC); K: tf32(acc); V: raw fp32
#pragma unroll
        for (int n = 0; n < 8; n++) {
            *(float2*)&g_Q[(size_t)r0 * Hv + n * 8 + 2 * t4] = make_float2(
                __uint_as_float(f2tf(acc[0][n][0] * QSC)), __uint_as_float(f2tf(acc[0][n][1] * QSC)));
            *(float2*)&g_Q[(size_t)(r0 + 8) * Hv + n * 8 + 2 * t4] = make_float2(
                __uint_as_float(f2tf(acc[0][n][2] * QSC)), __uint_as_float(f2tf(acc[0][n][3] * QSC)));
            *(float2*)&g_K[(size_t)r0 * Hv + n * 8 + 2 * t4] = make_float2(
                __uint_as_float(f2tf(acc[1][n][0])), __uint_as_float(f2tf(acc[1][n][1])));
            *(float2*)&g_K[(size_t)(r0 + 8) * Hv + n * 8 + 2 * t4] = make_float2(
                __uint_as_float(f2tf(acc[1][n][2])), __uint_as_float(f2tf(acc[1][n][3])));
            *(float2*)&g_V[(size_t)r0 * Hv + n * 8 + 2 * t4] =
                make_float2(acc[2][n][0], acc[2][n][1]);
            *(float2*)&g_V[(size_t)(r0 + 8) * Hv + n * 8 + 2 * t4] =
                make_float2(acc[2][n][2], acc[2][n][3]);
        }
    } else {
        const int gt = t - 128;
        const int xr = gt >> 1, xs = gt & 1;
        const int wn = gt & 63, wkh = (gt >> 6) * 16;
        const float* Wmat[3] = {Wq, Wk, Wv};
        unsigned* Xw = psmem;
        for (int it = 0; it < 32; it++) {
            const int p = it & 1, k0 = it * 32;
            if (it >= 2) BAR_SYNC(3 + p);
            unsigned* Xp = Xw + p * 2304;
            unsigned* Wp = Xw + 4608 + p * 6912;
            {
                const float4* xg = (const float4*)(x + (size_t)(m0 + xr) * Cv + k0 + 16 * xs);
#pragma unroll
                for (int c = 0; c < 4; c++) {
                    float4 v = xg[c];
                    *(uint4*)&Xp[xr * 36 + 16 * xs + 4 * c] =
                        make_uint4(f2tf(v.x), f2tf(v.y), f2tf(v.z), f2tf(v.w));
                }
            }
#pragma unroll
            for (int mat = 0; mat < 3; mat++) {
                const float* wg = Wmat[mat] + (size_t)(k0 + wkh) * Hv + wn;
                unsigned* Wd = Wp + mat * 2304 + wn * 36 + wkh;
#pragma unroll
                for (int j = 0; j < 16; j++)
                    Wd[j] = f2tf(wg[(size_t)j * Hv]);
            }
            BAR_ARRIVE(1 + p);
        }
    }
}

// ---------------------------------------------------------------------------
// V transpose: g_V [b*Tv+tk][h] (fp32) -> g_Vt [b*64+h][tk] (tf32 bits)
// ---------------------------------------------------------------------------
__global__ __launch_bounds__(256) void vt_kernel()
{
    __shared__ float sm[64 * 65];
    const int t = threadIdx.x;
    const int tk0 = blockIdx.x * 64, b = blockIdx.y;

    {
        const int r = t >> 2, c0 = (t & 3) * 16;
        const float4* vg = (const float4*)(g_V + (size_t)(b * Tv + tk0 + r) * Hv + c0);
#pragma unroll
        for (int c = 0; c < 4; c++) {
            float4 v = vg[c];
            sm[r * 65 + c0 + 4 * c + 0] = v.x;
            sm[r * 65 + c0 + 4 * c + 1] = v.y;
            sm[r * 65 + c0 + 4 * c + 2] = v.z;
            sm[r * 65 + c0 + 4 * c + 3] = v.w;
        }
    }
    __syncthreads();
    {
        const int h = t >> 2, i0 = (t & 3) * 16;
        unsigned* dst = (unsigned*)(g_Vt + (size_t)(b * 64 + h) * Tv + tk0 + i0);
#pragma unroll
        for (int c = 0; c < 4; c++) {
            *(uint4*)&dst[4 * c] = make_uint4(
                f2tf(sm[(i0 + 4 * c + 0) * 65 + h]), f2tf(sm[(i0 + 4 * c + 1) * 65 + h]),
                f2tf(sm[(i0 + 4 * c + 2) * 65 + h]), f2tf(sm[(i0 + 4 * c + 3) * 65 + h]));
        }
    }
}

// ---------------------------------------------------------------------------
// Flash attention: 8 compute warps (warp = 16 q-rows x 32-key half), cp.async
// double-buffered K/Vt, end-of-kernel pair merge.
// smem words: K[2][64][68] @0/4352; Vt[2][64][68] @8704/13056; Q[64][68] @17408;
// P[8][16][36] @21760.  Total 26368 words = 105472 B.
// ---------------------------------------------------------------------------
__device__ __forceinline__ void issue_tile(unsigned sb, int b, int kt, int p,
                                           int lr, int c4) {
    const float* kg = g_K + ((size_t)(b * Tv + kt * 64 + lr) << 6) + c4 * 16;
    unsigned kd = sb + p * 17408u + lr * 272u + c4 * 64u;
#pragma unroll
    for (int i = 0; i < 4; i++) CP_ASYNC16(kd + i * 16, (const char*)kg + i * 16);
    const float* vg = g_Vt + ((size_t)(b * 64 + lr) << 11) + kt * 64 + c4 * 16;
    unsigned vd = sb + 34816u + p * 17408u + lr * 272u + c4 * 64u;
#pragma unroll
    for (int i = 0; i < 4; i++) CP_ASYNC16(vd + i * 16, (const char*)vg + i * 16);
}

__global__ __launch_bounds__(256, 2) void attn_kernel(float* __restrict__ out)
{
    extern __shared__ unsigned asmem[];
    const unsigned sb = smem_u32(asmem);
    const int t = threadIdx.x, lane = t & 31, w = t >> 5;
    const int g = lane >> 2, t4 = lane & 3;

    const int bid = blockIdx.x;
    int qtile, b;
    if (bid < 108)      { qtile = bid % 27;      b = bid / 27; }
    else if (bid < 148) { int e = bid - 108; qtile = 27 + e % 5; b = e / 5; }
    else                { int v = 363 - bid; qtile = v % 27;     b = v / 27; }
    const int q0 = qtile * 64;

    const int lr = t >> 2, c4 = t & 3;   // cp.async row / chunk group

    // ---- prologue: Q + tile0 (group 0), tile1 (group 1) ----
    {
        const float* qg = g_Q + ((size_t)(b * Tv + q0 + lr) << 6) + c4 * 16;
        unsigned qd = sb + 69632u + lr * 272u + c4 * 64u;
#pragma unroll
        for (int i = 0; i < 4; i++) CP_ASYNC16(qd + i * 16, (const char*)qg + i * 16);
    }
    issue_tile(sb, b, 0, 0, lr, c4);
    CP_COMMIT();
    if (qtile >= 1) issue_tile(sb, b, 1, 1, lr, c4);
    CP_COMMIT();

    // fragment addressing
    const int rbase  = ((lane >> 4) << 3) + (lane & 7);
    const int coff   = ((lane >> 3) & 1) * 16;
    const int arbase = (((lane >> 3) & 1) << 3) + (lane & 7);
    const int acoff  = (lane >> 4) * 16;
    const int mr = (w >> 1) * 16;        // this warp's query rows
    const int kh = (w & 1) * 32;         // this warp's key half
    const unsigned qaddr = sb + 69632u + (mr + arbase) * 272 + acoff;
    const unsigned paddr = sb + 87040u + w * 2304 + arbase * 144 + acoff;
    unsigned* Pw = asmem + 21760 + w * 576;

    float o[8][4];
#pragma unroll
    for (int n = 0; n < 8; n++)
#pragma unroll
        for (int i = 0; i < 4; i++) o[n][i] = 0.f;
    float mrow0 = NEG, mrow1 = NEG, lrow0 = 0.f, lrow1 = 0.f;

    for (int kt = 0; kt <= qtile; kt++) {
        const int p = kt & 1;
        CP_WAIT1();
        __syncthreads();
        const unsigned kaddr = sb + p * 17408u + (kh + rbase) * 272 + coff;
        const unsigned vaddr = sb + 34816u + p * 17408u + rbase * 272 + coff + kh * 4;

        // ---- S = Q @ K^T (m16 x n32 x k64) ----
        float s[4][4];
#pragma unroll
        for (int n = 0; n < 4; n++)
#pragma unroll
            for (int i = 0; i < 4; i++) s[n][i] = 0.f;
#pragma unroll
        for (int ks = 0; ks < 8; ks++) {
            unsigned qa[4];
            LDSM4(qa[0], qa[1], qa[2], qa[3], qaddr + ks * 32);
#pragma unroll
            for (int jp = 0; jp < 2; jp++) {
                unsigned b0, b1, b2, b3;
                LDSM4(b0, b1, b2, b3, kaddr + jp * 4352 + ks * 32);
                unsigned blo[2] = {b0, b1}, bhi[2] = {b2, b3};
                mma_tf32(s[2 * jp], qa, blo);
                mma_tf32(s[2 * jp + 1], qa, bhi);
            }
        }

        if (kt == qtile) {   // causal mask on diagonal tile
            const int rl = mr + g, rh = rl + 8;
#pragma unroll
            for (int n = 0; n < 4; n++) {
                const int c0 = kh + n * 8 + 2 * t4;
                if (c0 > rl)     s[n][0] = NEG;
                if (c0 + 1 > rl) s[n][1] = NEG;
                if (c0 > rh)     s[n][2] = NEG;
                if (c0 + 1 > rh) s[n][3] = NEG;
            }
        }

        // ---- online softmax (base 2), warp-local ----
        float mx0 = NEG, mx1 = NEG;
#pragma unroll
        for (int n = 0; n < 4; n++) {
            mx0 = fmaxf(mx0, fmaxf(s[n][0], s[n][1]));
            mx1 = fmaxf(mx1, fmaxf(s[n][2], s[n][3]));
        }
        mx0 = fmaxf(mx0, __shfl_xor_sync(0xffffffffu, mx0, 1));
        mx0 = fmaxf(mx0, __shfl_xor_sync(0xffffffffu, mx0, 2));
        mx1 = fmaxf(mx1, __shfl_xor_sync(0xffffffffu, mx1, 1));
        mx1 = fmaxf(mx1, __shfl_xor_sync(0xffffffffu, mx1, 2));

        const float mn0 = fmaxf(mrow0, mx0), mn1 = fmaxf(mrow1, mx1);
        const float c0f = ex2f(mrow0 - mn0), c1f = ex2f(mrow1 - mn1);
        float ls0 = 0.f, ls1 = 0.f;
#pragma unroll
        for (int n = 0; n < 4; n++) {
            s[n][0] = ex2f(s[n][0] - mn0);
            s[n][1] = ex2f(s[n][1] - mn0);
            s[n][2] = ex2f(s[n][2] - mn1);
            s[n][3] = ex2f(s[n][3] - mn1);
            ls0 += s[n][0] + s[n][1];
            ls1 += s[n][2] + s[n][3];
        }
        ls0 += __shfl_xor_sync(0xffffffffu, ls0, 1);
        ls0 += __shfl_xor_sync(0xffffffffu, ls0, 2);
        ls1 += __shfl_xor_sync(0xffffffffu, ls1, 1);
        ls1 += __shfl_xor_sync(0xffffffffu, ls1, 2);
        lrow0 = lrow0 * c0f + ls0;
        lrow1 = lrow1 * c1f + ls1;
        mrow0 = mn0;
        mrow1 = mn1;
#pragma unroll
        for (int n = 0; n < 8; n++) {
            o[n][0] *= c0f; o[n][1] *= c0f;
            o[n][2] *= c1f; o[n][3] *= c1f;
        }

        // ---- P -> warp-private smem [16][36] ----
#pragma unroll
        for (int n = 0; n < 4; n++) {
            *(uint2*)&Pw[g * 36 + n * 8 + 2 * t4] =
                make_uint2(f2tf(s[n][0]), f2tf(s[n][1]));
            *(uint2*)&Pw[(g + 8) * 36 + n * 8 + 2 * t4] =
                make_uint2(f2tf(s[n][2]), f2tf(s[n][3]));
        }
        __syncwarp();

        // ---- O += P @ V (m16 x n64 x k32) ----
#pragma unroll
        for (int ks = 0; ks < 4; ks++) {
            unsigned pa[4];
            LDSM4(pa[0], pa[1], pa[2], pa[3], paddr + ks * 32);
#pragma unroll
            for (int jp = 0; jp < 4; jp++) {
                unsigned b0, b1, b2, b3;
                LDSM4(b0, b1, b2, b3, vaddr + jp * 4352 + ks * 32);
                unsigned blo[2] = {b0, b1}, bhi[2] = {b2, b3};
                mma_tf32(o[2 * jp], pa, blo);
                mma_tf32(o[2 * jp + 1], pa, bhi);
            }
        }
        __syncthreads();
        if (kt + 2 <= qtile) issue_tile(sb, b, kt + 2, p, lr, c4);
        CP_COMMIT();
    }

    // ---- pair merge: odd warp (key half 1) -> smem; even combines + stores ----
    const int u = w >> 1;
    float* Osm = (float*)asmem + u * 1088;        // [16][68]
    float* Ml  = (float*)asmem + 4352 + u * 32;   // [16][2]
    if (w & 1) {
#pragma unroll
        for (int n = 0; n < 8; n++) {
            *(float2*)&Osm[g * 68 + n * 8 + 2 * t4] = make_float2(o[n][0], o[n][1]);
            *(float2*)&Osm[(g + 8) * 68 + n * 8 + 2 * t4] = make_float2(o[n][2], o[n][3]);
        }
        if (t4 == 0) {
            Ml[g * 2] = mrow0;       Ml[g * 2 + 1] = lrow0;
            Ml[(g + 8) * 2] = mrow1; Ml[(g + 8) * 2 + 1] = lrow1;
        }
    }
    __syncthreads();
    if (!(w & 1)) {
        const float m2a = Ml[g * 2], l2a = Ml[g * 2 + 1];
        const float m2b = Ml[(g + 8) * 2], l2b = Ml[(g + 8) * 2 + 1];
        const float M0 = fmaxf(mrow0, m2a), M1 = fmaxf(mrow1, m2b);
        const float c1a = ex2f(mrow0 - M0), c2a = ex2f(m2a - M0);
        const float c1b = ex2f(mrow1 - M1), c2b = ex2f(m2b - M1);
        const float inv0 = 1.f / (lrow0 * c1a + l2a * c2a);
        const float inv1 = 1.f / (lrow1 * c1b + l2b * c2b);
        const size_t ro = (size_t)(b * Tv + q0 + mr + g) * Hv;
#pragma unroll
        for (int n = 0; n < 8; n++) {
            float2 pa = *(float2*)&Osm[g * 68 + n * 8 + 2 * t4];
            float2 pb = *(float2*)&Osm[(g + 8) * 68 + n * 8 + 2 * t4];
            *(float2*)&out[ro + n * 8 + 2 * t4] =
                make_float2((o[n][0] * c1a + pa.x * c2a) * inv0,
                            (o[n][1] * c1a + pa.y * c2a) * inv0);
            *(float2*)&out[ro + 8 * Hv + n * 8 + 2 * t4] =
                make_float2((o[n][2] * c1b + pb.x * c2b) * inv1,
                            (o[n][3] * c1b + pb.y * c2b) * inv1);
        }
    }
}

// ---------------------------------------------------------------------------
extern "C" void kernel_launch(void* const* d_in, const int* in_sizes, int n_in,
                              void* d_out, int out_size)
{
    const float* x  = (const float*)d_in[0];
    const float* Wq = (const float*)d_in[1];
    const float* Wk = (const float*)d_in[2];
    const float* Wv = (const float*)d_in[3];
    float* out = (float*)d_out;

    const int proj_smem = 18432 + 55296;   // 73,728 B
    const int attn_smem = 105472;          // see layout above
    cudaFuncSetAttribute(proj_kernel, cudaFuncAttributeMaxDynamicSharedMemorySize, proj_smem);
    cudaFuncSetAttribute(attn_kernel, cudaFuncAttributeMaxDynamicSharedMemorySize, attn_smem);

    proj_kernel<<<Mtot / 64, 256, proj_smem>>>(x, Wq, Wk, Wv);
    vt_kernel<<<dim3(Tv / 64, Bv), 256>>>();
    attn_kernel<<<256, 256, attn_smem>>>(out);
}

// round 9
// speedup vs baseline: 11.8824x; 1.8208x over previous
#include <cuda_runtime.h>
#include <cuda_fp16.h>
#include <cstdint>
#include <math.h>

constexpr int Bv = 8, Tv = 2048, Cv = 1024, Hv = 64;
constexpr int Mtot = Bv * Tv;

__device__ __half g_Qh[Mtot * Hv];      // fp16, pre-scaled by 0.125*log2(e)
__device__ __half g_Kh[Mtot * Hv];      // fp16
__device__ float  g_V[Mtot * Hv];       // fp32 (proj output)
__device__ __half g_Vth[Bv * Hv * Tv];  // fp16, transposed [b*64+h][token]

__device__ __forceinline__ float ex2f(float f) {
    float r; asm("ex2.approx.ftz.f32 %0, %1;" : "=f"(r) : "f"(f)); return r;
}
__device__ __forceinline__ unsigned smem_u32(const void* p) {
    unsigned a; asm("{ .reg .u64 t; cvta.to.shared.u64 t, %1; cvt.u32.u64 %0, t; }" : "=r"(a) : "l"(p)); return a;
}
__device__ __forceinline__ void mma_f16(float* c, const unsigned* a, const unsigned* b) {
    asm volatile(
        "mma.sync.aligned.m16n8k16.row.col.f32.f16.f16.f32 "
        "{%0,%1,%2,%3}, {%4,%5,%6,%7}, {%8,%9}, {%0,%1,%2,%3};"
        : "+f"(c[0]), "+f"(c[1]), "+f"(c[2]), "+f"(c[3])
        : "r"(a[0]), "r"(a[1]), "r"(a[2]), "r"(a[3]), "r"(b[0]), "r"(b[1]));
}
#define LDSM4(r0, r1, r2, r3, a) \
    asm volatile("ldmatrix.sync.aligned.m8n8.x4.shared.b16 {%0,%1,%2,%3}, [%4];" \
                 : "=r"(r0), "=r"(r1), "=r"(r2), "=r"(r3) : "r"(a))
#define BAR_SYNC(id)   asm volatile("bar.sync %0, %1;"   :: "r"(id), "r"(256) : "memory")
#define BAR_ARRIVE(id) asm volatile("bar.arrive %0, %1;" :: "r"(id), "r"(256) : "memory")
#define CP_ASYNC16(s, g) asm volatile("cp.async.cg.shared.global [%0], [%1], 16;" :: "r"(s), "l"(g))
#define CP_COMMIT()      asm volatile("cp.async.commit_group;" ::: "memory")
#define CP_WAIT1()       asm volatile("cp.async.wait_group 1;" ::: "memory")

constexpr float QSC = 0.18033688f;   // 0.125 * log2(e)
constexpr float NEG = -1e30f;

// ---------------------------------------------------------------------------
// Fused QKV projection, fp16 fragments. 256 thr: warps 0-3 consume (m16 tile
// each), warps 4-7 produce. 2-stage, BK=32.
// smem (bytes): X[2][64][40h] @0 (5120/stage); W[2][3][64][40h] @10240 (15360/stage)
// ---------------------------------------------------------------------------
__global__ __launch_bounds__(256, 2) void proj_kernel(
    const float* __restrict__ x,
    const float* __restrict__ Wq,
    const float* __restrict__ Wk,
    const float* __restrict__ Wv)
{
    extern __shared__ __align__(16) char psm[];
    const unsigned sb = smem_u32(psm);

    const int t = threadIdx.x, lane = t & 31, w = t >> 5;
    const int g = lane >> 2, t4 = lane & 3;
    const int m0 = blockIdx.x * 64;

    if (w < 4) {
        // ------------------ consumers ------------------
        const int rbase = ((lane >> 4) << 3) + (lane & 7);
        const int coff  = ((lane >> 3) & 1) * 16;
        const int ar    = lane & 15;
        const int acoff = (lane >> 4) * 16;
        const int mt = w;

        float acc[3][8][4];
#pragma unroll
        for (int a = 0; a < 3; a++)
#pragma unroll
            for (int n = 0; n < 8; n++)
#pragma unroll
                for (int i = 0; i < 4; i++) acc[a][n][i] = 0.f;

        for (int it = 0; it < 32; it++) {
            const int p = it & 1;
            BAR_SYNC(1 + p);
            const unsigned aaddr = sb + p * 5120u + (mt * 16 + ar) * 80 + acoff;
            const unsigned bbase = sb + 10240u + p * 15360u + rbase * 80 + coff;
#pragma unroll
            for (int ks = 0; ks < 2; ks++) {
                unsigned a[4];
                LDSM4(a[0], a[1], a[2], a[3], aaddr + ks * 32);
#pragma unroll
                for (int mat = 0; mat < 3; mat++) {
#pragma unroll
                    for (int j = 0; j < 4; j++) {
                        unsigned b0, b1, b2, b3;
                        LDSM4(b0, b1, b2, b3, bbase + mat * 5120 + j * 1280 + ks * 32);
                        unsigned blo[2] = {b0, b1}, bhi[2] = {b2, b3};
                        mma_f16(acc[mat][2 * j], a, blo);
                        mma_f16(acc[mat][2 * j + 1], a, bhi);
                    }
                }
            }
            BAR_ARRIVE(3 + p);
        }

        const int r0 = m0 + mt * 16 + g;
#pragma unroll
        for (int n = 0; n < 8; n++) {
            *(__half2*)&g_Qh[(size_t)r0 * Hv + n * 8 + 2 * t4] =
                __floats2half2_rn(acc[0][n][0] * QSC, acc[0][n][1] * QSC);
            *(__half2*)&g_Qh[(size_t)(r0 + 8) * Hv + n * 8 + 2 * t4] =
                __floats2half2_rn(acc[0][n][2] * QSC, acc[0][n][3] * QSC);
            *(__half2*)&g_Kh[(size_t)r0 * Hv + n * 8 + 2 * t4] =
                __floats2half2_rn(acc[1][n][0], acc[1][n][1]);
            *(__half2*)&g_Kh[(size_t)(r0 + 8) * Hv + n * 8 + 2 * t4] =
                __floats2half2_rn(acc[1][n][2], acc[1][n][3]);
            *(float2*)&g_V[(size_t)r0 * Hv + n * 8 + 2 * t4] =
                make_float2(acc[2][n][0], acc[2][n][1]);
            *(float2*)&g_V[(size_t)(r0 + 8) * Hv + n * 8 + 2 * t4] =
                make_float2(acc[2][n][2], acc[2][n][3]);
        }
    } else {
        // ------------------ producers ------------------
        const int gt = t - 128;
        const int xr = gt >> 1, xs = gt & 1;          // X: row m, k-half16
        const int wn = gt & 63, wkh = (gt >> 6) * 16; // W: col n, k-half16
        const float* Wmat[3] = {Wq, Wk, Wv};
        __half* Xs = (__half*)psm;
        __half* Ws = (__half*)(psm + 10240);
        for (int it = 0; it < 32; it++) {
            const int p = it & 1, k0 = it * 32;
            if (it >= 2) BAR_SYNC(3 + p);
            __half* Xp = Xs + p * 2560;
            __half* Wp = Ws + p * 7680;
            // X tile [64 m][32 k] fp16, rows 40 halves
            {
                const float4* xg = (const float4*)(x + (size_t)(m0 + xr) * Cv + k0 + 16 * xs);
                __half2 h[8];
#pragma unroll
                for (int c = 0; c < 4; c++) {
                    float4 v = xg[c];
                    h[2 * c]     = __floats2half2_rn(v.x, v.y);
                    h[2 * c + 1] = __floats2half2_rn(v.z, v.w);
                }
                *(uint4*)&Xp[xr * 40 + 16 * xs]     = *(uint4*)&h[0];
                *(uint4*)&Xp[xr * 40 + 16 * xs + 8] = *(uint4*)&h[4];
            }
            // W tiles transposed [n][k] fp16
#pragma unroll
            for (int mat = 0; mat < 3; mat++) {
                const float* wg = Wmat[mat] + (size_t)(k0 + wkh) * Hv + wn;
                __half2 h[8];
#pragma unroll
                for (int j = 0; j < 8; j++)
                    h[j] = __floats2half2_rn(wg[(size_t)(2 * j) * Hv], wg[(size_t)(2 * j + 1) * Hv]);
                __half* Wd = Wp + mat * 2560 + wn * 40 + wkh;
                *(uint4*)&Wd[0] = *(uint4*)&h[0];
                *(uint4*)&Wd[8] = *(uint4*)&h[4];
            }
            BAR_ARRIVE(1 + p);
        }
    }
}

// ---------------------------------------------------------------------------
// V transpose: g_V [b*Tv+tk][h] fp32 -> g_Vth [b*64+h][tk] fp16
// ---------------------------------------------------------------------------
__global__ __launch_bounds__(256) void vt_kernel()
{
    __shared__ float sm[64 * 65];
    const int t = threadIdx.x;
    const int tk0 = blockIdx.x * 64, b = blockIdx.y;

    {
        const int r = t >> 2, c0 = (t & 3) * 16;
        const float4* vg = (const float4*)(g_V + (size_t)(b * Tv + tk0 + r) * Hv + c0);
#pragma unroll
        for (int c = 0; c < 4; c++) {
            float4 v = vg[c];
            sm[r * 65 + c0 + 4 * c + 0] = v.x;
            sm[r * 65 + c0 + 4 * c + 1] = v.y;
            sm[r * 65 + c0 + 4 * c + 2] = v.z;
            sm[r * 65 + c0 + 4 * c + 3] = v.w;
        }
    }
    __syncthreads();
    {
        const int hh = t >> 2, i0 = (t & 3) * 16;
        __half2 h[8];
#pragma unroll
        for (int c = 0; c < 8; c++)
            h[c] = __floats2half2_rn(sm[(i0 + 2 * c) * 65 + hh], sm[(i0 + 2 * c + 1) * 65 + hh]);
        __half* dst = g_Vth + (size_t)(b * 64 + hh) * Tv + tk0 + i0;
        *(uint4*)&dst[0] = *(uint4*)&h[0];
        *(uint4*)&dst[8] = *(uint4*)&h[4];
    }
}

// ---------------------------------------------------------------------------
// Flash attention fp16: 8 compute warps (warp = 16 q-rows x 32-key half),
// cp.async double-buffered, end pair-merge.
// smem bytes: K[2][64][72h] @0 (9216/stage); Vt[2][64][72h] @18432;
//             Q[64][72h] @36864; P[8][16][40h] @46080.  Total 56320 B.
// ---------------------------------------------------------------------------
__device__ __forceinline__ void issue_tile(unsigned sb, int b, int kt, int p,
                                           int lr, int c4) {
    const __half* kg = g_Kh + ((size_t)(b * Tv + kt * 64 + lr) << 6) + c4 * 16;
    unsigned kd = sb + p * 9216u + lr * 144u + c4 * 32u;
    CP_ASYNC16(kd, kg);
    CP_ASYNC16(kd + 16, kg + 8);
    const __half* vg = g_Vth + ((size_t)(b * 64 + lr) << 11) + kt * 64 + c4 * 16;
    unsigned vd = sb + 18432u + p * 9216u + lr * 144u + c4 * 32u;
    CP_ASYNC16(vd, vg);
    CP_ASYNC16(vd + 16, vg + 8);
}

__global__ __launch_bounds__(256, 2) void attn_kernel(float* __restrict__ out)
{
    extern __shared__ __align__(16) char asm_[];
    const unsigned sb = smem_u32(asm_);
    const int t = threadIdx.x, lane = t & 31, w = t >> 5;
    const int g = lane >> 2, t4 = lane & 3;

    const int bid = blockIdx.x;
    int qtile, b;
    if (bid < 108)      { qtile = bid % 27;      b = bid / 27; }
    else if (bid < 148) { int e = bid - 108; qtile = 27 + e % 5; b = e / 5; }
    else                { int v = 363 - bid; qtile = v % 27;     b = v / 27; }
    const int q0 = qtile * 64;

    const int lr = t >> 2, c4 = t & 3;

    // ---- prologue loads ----
    {
        const __half* qg = g_Qh + ((size_t)(b * Tv + q0 + lr) << 6) + c4 * 16;
        unsigned qd = sb + 36864u + lr * 144u + c4 * 32u;
        CP_ASYNC16(qd, qg);
        CP_ASYNC16(qd + 16, qg + 8);
    }
    issue_tile(sb, b, 0, 0, lr, c4);
    CP_COMMIT();
    if (qtile >= 1) issue_tile(sb, b, 1, 1, lr, c4);
    CP_COMMIT();

    // fragment addressing
    const int rbase = ((lane >> 4) << 3) + (lane & 7);
    const int coff  = ((lane >> 3) & 1) * 16;
    const int ar    = lane & 15;
    const int acoff = (lane >> 4) * 16;
    const int mr = (w >> 1) * 16;        // query rows
    const int kh = (w & 1) * 32;         // key half
    const unsigned qaddr = sb + 36864u + (mr + ar) * 144 + acoff;
    const unsigned paddr = sb + 46080u + w * 1280 + ar * 80 + acoff;
    __half* Pw = (__half*)(asm_ + 46080 + w * 1280);

    float o[8][4];
#pragma unroll
    for (int n = 0; n < 8; n++)
#pragma unroll
        for (int i = 0; i < 4; i++) o[n][i] = 0.f;
    float mrow0 = NEG, mrow1 = NEG, lrow0 = 0.f, lrow1 = 0.f;

    for (int kt = 0; kt <= qtile; kt++) {
        const int p = kt & 1;
        CP_WAIT1();
        __syncthreads();
        const unsigned kaddr = sb + p * 9216u + (kh + rbase) * 144 + coff;
        const unsigned vaddr = sb + 18432u + p * 9216u + rbase * 144 + coff + kh * 2;

        // ---- S = Q @ K^T (m16 x n32 x k64) ----
        float s[4][4];
#pragma unroll
        for (int n = 0; n < 4; n++)
#pragma unroll
            for (int i = 0; i < 4; i++) s[n][i] = 0.f;
#pragma unroll
        for (int ks = 0; ks < 4; ks++) {
            unsigned qa[4];
            LDSM4(qa[0], qa[1], qa[2], qa[3], qaddr + ks * 32);
#pragma unroll
            for (int jp = 0; jp < 2; jp++) {
                unsigned b0, b1, b2, b3;
                LDSM4(b0, b1, b2, b3, kaddr + jp * 2304 + ks * 32);
                unsigned blo[2] = {b0, b1}, bhi[2] = {b2, b3};
                mma_f16(s[2 * jp], qa, blo);
                mma_f16(s[2 * jp + 1], qa, bhi);
            }
        }

        if (kt == qtile) {   // causal mask on diagonal tile
            const int rl = mr + g, rh = rl + 8;
#pragma unroll
            for (int n = 0; n < 4; n++) {
                const int c0 = kh + n * 8 + 2 * t4;
                if (c0 > rl)     s[n][0] = NEG;
                if (c0 + 1 > rl) s[n][1] = NEG;
                if (c0 > rh)     s[n][2] = NEG;
                if (c0 + 1 > rh) s[n][3] = NEG;
            }
        }

        // ---- online softmax (base 2), warp-local ----
        float mx0 = NEG, mx1 = NEG;
#pragma unroll
        for (int n = 0; n < 4; n++) {
            mx0 = fmaxf(mx0, fmaxf(s[n][0], s[n][1]));
            mx1 = fmaxf(mx1, fmaxf(s[n][2], s[n][3]));
        }
        mx0 = fmaxf(mx0, __shfl_xor_sync(0xffffffffu, mx0, 1));
        mx0 = fmaxf(mx0, __shfl_xor_sync(0xffffffffu, mx0, 2));
        mx1 = fmaxf(mx1, __shfl_xor_sync(0xffffffffu, mx1, 1));
        mx1 = fmaxf(mx1, __shfl_xor_sync(0xffffffffu, mx1, 2));

        const float mn0 = fmaxf(mrow0, mx0), mn1 = fmaxf(mrow1, mx1);
        const float c0f = ex2f(mrow0 - mn0), c1f = ex2f(mrow1 - mn1);
        float ls0 = 0.f, ls1 = 0.f;
#pragma unroll
        for (int n = 0; n < 4; n++) {
            s[n][0] = ex2f(s[n][0] - mn0);
            s[n][1] = ex2f(s[n][1] - mn0);
            s[n][2] = ex2f(s[n][2] - mn1);
            s[n][3] = ex2f(s[n][3] - mn1);
            ls0 += s[n][0] + s[n][1];
            ls1 += s[n][2] + s[n][3];
        }
        ls0 += __shfl_xor_sync(0xffffffffu, ls0, 1);
        ls0 += __shfl_xor_sync(0xffffffffu, ls0, 2);
        ls1 += __shfl_xor_sync(0xffffffffu, ls1, 1);
        ls1 += __shfl_xor_sync(0xffffffffu, ls1, 2);
        lrow0 = lrow0 * c0f + ls0;
        lrow1 = lrow1 * c1f + ls1;
        mrow0 = mn0;
        mrow1 = mn1;
#pragma unroll
        for (int n = 0; n < 8; n++) {
            o[n][0] *= c0f; o[n][1] *= c0f;
            o[n][2] *= c1f; o[n][3] *= c1f;
        }

        // ---- P -> warp-private smem [16][40] halves ----
#pragma unroll
        for (int n = 0; n < 4; n++) {
            *(__half2*)&Pw[g * 40 + n * 8 + 2 * t4] =
                __floats2half2_rn(s[n][0], s[n][1]);
            *(__half2*)&Pw[(g + 8) * 40 + n * 8 + 2 * t4] =
                __floats2half2_rn(s[n][2], s[n][3]);
        }
        __syncwarp();

        // ---- O += P @ V (m16 x n64 x k32) ----
#pragma unroll
        for (int ks = 0; ks < 2; ks++) {
            unsigned pa[4];
            LDSM4(pa[0], pa[1], pa[2], pa[3], paddr + ks * 32);
#pragma unroll
            for (int jp = 0; jp < 4; jp++) {
                unsigned b0, b1, b2, b3;
                LDSM4(b0, b1, b2, b3, vaddr + jp * 2304 + ks * 32);
                unsigned blo[2] = {b0, b1}, bhi[2] = {b2, b3};
                mma_f16(o[2 * jp], pa, blo);
                mma_f16(o[2 * jp + 1], pa, bhi);
            }
        }
        __syncthreads();
        if (kt + 2 <= qtile) issue_tile(sb, b, kt + 2, p, lr, c4);
        CP_COMMIT();
    }

    // ---- pair merge: odd warp -> smem; even combines + stores ----
    const int u = w >> 1;
    float* Osm = (float*)asm_ + u * 1088;        // [16][68]
    float* Ml  = (float*)asm_ + 4352 + u * 32;   // [16][2]
    if (w & 1) {
#pragma unroll
        for (int n = 0; n < 8; n++) {
            *(float2*)&Osm[g * 68 + n * 8 + 2 * t4] = make_float2(o[n][0], o[n][1]);
            *(float2*)&Osm[(g + 8) * 68 + n * 8 + 2 * t4] = make_float2(o[n][2], o[n][3]);
        }
        if (t4 == 0) {
            Ml[g * 2] = mrow0;       Ml[g * 2 + 1] = lrow0;
            Ml[(g + 8) * 2] = mrow1; Ml[(g + 8) * 2 + 1] = lrow1;
        }
    }
    __syncthreads();
    if (!(w & 1)) {
        const float m2a = Ml[g * 2], l2a = Ml[g * 2 + 1];
        const float m2b = Ml[(g + 8) * 2], l2b = Ml[(g + 8) * 2 + 1];
        const float M0 = fmaxf(mrow0, m2a), M1 = fmaxf(mrow1, m2b);
        const float c1a = ex2f(mrow0 - M0), c2a = ex2f(m2a - M0);
        const float c1b = ex2f(mrow1 - M1), c2b = ex2f(m2b - M1);
        const float inv0 = 1.f / (lrow0 * c1a + l2a * c2a);
        const float inv1 = 1.f / (lrow1 * c1b + l2b * c2b);
        const size_t ro = (size_t)(b * Tv + q0 + mr + g) * Hv;
#pragma unroll
        for (int n = 0; n < 8; n++) {
            float2 pa = *(float2*)&Osm[g * 68 + n * 8 + 2 * t4];
            float2 pb = *(float2*)&Osm[(g + 8) * 68 + n * 8 + 2 * t4];
            *(float2*)&out[ro + n * 8 + 2 * t4] =
                make_float2((o[n][0] * c1a + pa.x * c2a) * inv0,
                            (o[n][1] * c1a + pa.y * c2a) * inv0);
            *(float2*)&out[ro + 8 * Hv + n * 8 + 2 * t4] =
                make_float2((o[n][2] * c1b + pb.x * c2b) * inv1,
                            (o[n][3] * c1b + pb.y * c2b) * inv1);
        }
    }
}

// ---------------------------------------------------------------------------
extern "C" void kernel_launch(void* const* d_in, const int* in_sizes, int n_in,
                              void* d_out, int out_size)
{
    const float* x  = (const float*)d_in[0];
    const float* Wq = (const float*)d_in[1];
    const float* Wk = (const float*)d_in[2];
    const float* Wv = (const float*)d_in[3];
    float* out = (float*)d_out;

    const int proj_smem = 40960;
    const int attn_smem = 56320;
    cudaFuncSetAttribute(proj_kernel, cudaFuncAttributeMaxDynamicSharedMemorySize, proj_smem);
    cudaFuncSetAttribute(attn_kernel, cudaFuncAttributeMaxDynamicSharedMemorySize, attn_smem);

    proj_kernel<<<Mtot / 64, 256, proj_smem>>>(x, Wq, Wk, Wv);
    vt_kernel<<<dim3(Tv / 64, Bv), 256>>>();
    attn_kernel<<<256, 256, attn_smem>>>(out);
}